// round 14
// baseline (speedup 1.0000x reference)
#include <cuda_runtime.h>
#include <math.h>
#include <stdint.h>

// B=4, L=1024, D=256, N_PER=48, N_HYP=16, K=64, features 2K=128
#define M_ROWS 4096
#define LDH 1280
#define PI_F 3.14159265358979323846f
#define TA_LD 36   // smem k-chunk stride (36 mod 32 = 4 -> conflict-free frags)

// scratch
__device__ float g_hid[M_ROWS * LDH];   // [GELU(kp|qp|kh|qh hidden) | V]
__device__ float g_k2[M_ROWS * 128];
__device__ float g_q2[M_ROWS * 128];
__device__ float g_ret[M_ROWS * 256];
__device__ float g_ret2[M_ROWS * 256];
__device__ float g_rln[M_ROWS * 256];

__device__ __forceinline__ float gelu_exact(float v) {
    return 0.5f * v * (1.0f + erff(v * 0.7071067811865475f));
}

// ---- cp.async helpers -----------------------------------------------------
__device__ __forceinline__ void cpa16(void* s, const void* g) {
    uint32_t sa = (uint32_t)__cvta_generic_to_shared(s);
    asm volatile("cp.async.cg.shared.global [%0], [%1], 16;" :: "r"(sa), "l"(g));
}
__device__ __forceinline__ void cpa16z(void* s, const void* g, int sz) {
    uint32_t sa = (uint32_t)__cvta_generic_to_shared(s);
    asm volatile("cp.async.cg.shared.global [%0], [%1], 16, %2;" :: "r"(sa), "l"(g), "r"(sz));
}
#define CP_COMMIT() asm volatile("cp.async.commit_group;" ::: "memory")
#define CP_WAIT(N)  asm volatile("cp.async.wait_group %0;" :: "n"(N) : "memory")

// raw fp32 bits fed to mma.tf32 (HW truncates to tf32)
__device__ __forceinline__ void mma8(float c[4], const uint32_t a[4], const uint32_t b[2]) {
    asm("mma.sync.aligned.m16n8k8.row.col.f32.tf32.tf32.f32 "
        "{%0,%1,%2,%3},{%4,%5,%6,%7},{%8,%9},{%0,%1,%2,%3};"
        : "+f"(c[0]), "+f"(c[1]), "+f"(c[2]), "+f"(c[3])
        : "r"(a[0]), "r"(a[1]), "r"(a[2]), "r"(a[3]), "r"(b[0]), "r"(b[1]));
}

// ===========================================================================
// Fused first layers: hid[4096,1280] = [GELU(x@W1^T+b1) x4 | x@v_w^T+v_b]
// 128x128 tiles, 2-stage pipe. grid (32, 10). warps 2(m) x 4(n).
// ===========================================================================
#define F1_SMEM_U32 (2 * 128 * TA_LD + 2 * 128 * TA_LD)   // 18432
#define F1_SMEM_BYTES (F1_SMEM_U32 * 4)                   // 73728

__global__ void __launch_bounds__(256) gemm_fused1(
    const float* __restrict__ x,
    const float* __restrict__ w0, const float* __restrict__ b0,
    const float* __restrict__ w1, const float* __restrict__ b1,
    const float* __restrict__ w2, const float* __restrict__ b2,
    const float* __restrict__ w3, const float* __restrict__ b3,
    const float* __restrict__ w4, const float* __restrict__ b4,
    float* __restrict__ hid)
{
    extern __shared__ float smf[];
    float* sA = smf;                        // 2 x 128*TA_LD
    float* sB = smf + 2 * 128 * TA_LD;      // 2 x 128*TA_LD
    const int tid = threadIdx.x, lane = tid & 31, wid = tid >> 5;
    const int group = lane >> 2, tig = lane & 3;
    const int warpM = wid & 1, warpN = wid >> 1;
    const int m0 = blockIdx.x * 128;
    const int by = blockIdx.y;
    const int seg = by >> 1;
    const int half = by & 1;

    const float* W; const float* Bs;
    if      (seg == 0) { W = w0; Bs = b0; }
    else if (seg == 1) { W = w1; Bs = b1; }
    else if (seg == 2) { W = w2; Bs = b2; }
    else if (seg == 3) { W = w3; Bs = b3; }
    else               { W = w4; Bs = b4; }
    W += (size_t)(half * 128) * 256;
    Bs += half * 128;
    const float* An = x + (size_t)m0 * 256;

    auto issue = [&](int k0, int st) {
        #pragma unroll
        for (int s = 0; s < 4; s++) {           // A: 128 x 32
            int slot = tid + s * 256;
            int r = slot >> 3;
            int kk = (slot & 7) << 2;
            cpa16(&sA[st * 128 * TA_LD + r * TA_LD + kk],
                  &An[(size_t)r * 256 + k0 + kk]);
        }
        #pragma unroll
        for (int s = 0; s < 4; s++) {           // W: 128 x 32
            int slot = tid + s * 256;
            int r = slot >> 3;
            int kk = (slot & 7) << 2;
            cpa16(&sB[st * 128 * TA_LD + r * TA_LD + kk],
                  &W[(size_t)r * 256 + k0 + kk]);
        }
    };

    float acc[4][4][4] = {};
    issue(0, 0);
    CP_COMMIT();
    int p = 0;
    #pragma unroll
    for (int c = 0; c < 8; c++) {
        if (c < 7) { issue((c + 1) * 32, p ^ 1); CP_COMMIT(); CP_WAIT(1); }
        else       { CP_WAIT(0); }
        __syncthreads();
        const uint32_t* uA = (const uint32_t*)(sA + p * 128 * TA_LD);
        const uint32_t* uB = (const uint32_t*)(sB + p * 128 * TA_LD);
        #pragma unroll
        for (int ks = 0; ks < 4; ks++) {
            int kb = ks * 8;
            uint32_t a[4][4], b[4][2];
            #pragma unroll
            for (int mf = 0; mf < 4; mf++) {
                int r0 = warpM * 64 + mf * 16 + group;
                a[mf][0] = uA[r0 * TA_LD + kb + tig];
                a[mf][1] = uA[(r0 + 8) * TA_LD + kb + tig];
                a[mf][2] = uA[r0 * TA_LD + kb + tig + 4];
                a[mf][3] = uA[(r0 + 8) * TA_LD + kb + tig + 4];
            }
            #pragma unroll
            for (int nf = 0; nf < 4; nf++) {
                int n0 = warpN * 32 + nf * 8 + group;
                b[nf][0] = uB[n0 * TA_LD + kb + tig];
                b[nf][1] = uB[n0 * TA_LD + kb + tig + 4];
            }
            #pragma unroll
            for (int mf = 0; mf < 4; mf++)
                #pragma unroll
                for (int nf = 0; nf < 4; nf++)
                    mma8(acc[mf][nf], a[mf], b[nf]);
        }
        __syncthreads();
        p ^= 1;
    }

    cudaTriggerProgrammaticLaunchCompletion();   // mainloop done; epilogue follows

    #pragma unroll
    for (int mf = 0; mf < 4; mf++) {
        int r0 = m0 + warpM * 64 + mf * 16 + group;
        #pragma unroll
        for (int nf = 0; nf < 4; nf++) {
            int colL = warpN * 32 + nf * 8 + 2 * tig;
            float bv0 = Bs[colL], bv1 = Bs[colL + 1];
            float v00 = acc[mf][nf][0] + bv0, v01 = acc[mf][nf][1] + bv1;
            float v10 = acc[mf][nf][2] + bv0, v11 = acc[mf][nf][3] + bv1;
            if (seg < 4) {
                v00 = gelu_exact(v00); v01 = gelu_exact(v01);
                v10 = gelu_exact(v10); v11 = gelu_exact(v11);
            }
            int gcol = by * 128 + colL;
            *(float2*)&hid[(size_t)r0 * LDH + gcol] = make_float2(v00, v01);
            *(float2*)&hid[(size_t)(r0 + 8) * LDH + gcol] = make_float2(v10, v11);
        }
    }
}

// ===========================================================================
// 128x64 tile engine (cp.async pipelined, 2-stage) — used by layer2_feat
// ===========================================================================
template <bool GUARD>
__device__ __forceinline__ void issue_chunk128(
    const float* __restrict__ A, int lda,
    const float* __restrict__ W, int nvalid, int k0,
    float* sA, float* sB)
{
    const int tid = threadIdx.x;
    #pragma unroll
    for (int s = 0; s < 4; s++) {                 // A: 128 x 32
        int slot = tid + s * 256;
        int r = slot >> 3;
        int kk = (slot & 7) << 2;
        cpa16(&sA[r * TA_LD + kk], &A[(size_t)r * lda + k0 + kk]);
    }
    #pragma unroll
    for (int s = 0; s < 2; s++) {                 // W: 64 x 32
        int slot = tid + s * 256;
        int r = slot >> 3;
        int kk = (slot & 7) << 2;
        if (GUARD) {
            int rr = (r < nvalid) ? r : 0;
            cpa16z(&sB[r * TA_LD + kk], &W[(size_t)rr * 256 + k0 + kk],
                   (r < nvalid) ? 16 : 0);
        } else {
            cpa16(&sB[r * TA_LD + kk], &W[(size_t)r * 256 + k0 + kk]);
        }
    }
}

__device__ __forceinline__ void gl_compute(
    const uint32_t* sA, const uint32_t* sB, float acc[2][4][4],
    int warpM, int warpN, int group, int tig)
{
    #pragma unroll
    for (int ks = 0; ks < 4; ks++) {
        int kb = ks * 8;
        uint32_t a[2][4], b[4][2];
        #pragma unroll
        for (int mf = 0; mf < 2; mf++) {
            int r0 = warpM * 32 + mf * 16 + group;
            a[mf][0] = sA[r0 * TA_LD + kb + tig];
            a[mf][1] = sA[(r0 + 8) * TA_LD + kb + tig];
            a[mf][2] = sA[r0 * TA_LD + kb + tig + 4];
            a[mf][3] = sA[(r0 + 8) * TA_LD + kb + tig + 4];
        }
        #pragma unroll
        for (int nf = 0; nf < 4; nf++) {
            int n0 = warpN * 32 + nf * 8 + group;
            b[nf][0] = sB[n0 * TA_LD + kb + tig];
            b[nf][1] = sB[n0 * TA_LD + kb + tig + 4];
        }
        #pragma unroll
        for (int mf = 0; mf < 2; mf++)
            #pragma unroll
            for (int nf = 0; nf < 4; nf++)
                mma8(acc[mf][nf], a[mf], b[nf]);
    }
}

#define GEMM_SMEM_U32 (2 * 128 * TA_LD + 2 * 64 * TA_LD)   // 13824
#define GEMM_SMEM_BYTES (GEMM_SMEM_U32 * 4)

template <bool GUARD>
__device__ __forceinline__ void tile_mma_pipe(
    const float* __restrict__ A, int lda,
    const float* __restrict__ W, int nvalid,
    float* smf, float acc[2][4][4],
    int warpM, int warpN, int group, int tig)
{
    float* sA = smf;                       // 2 x 128*TA_LD
    float* sB = smf + 2 * 128 * TA_LD;     // 2 x 64*TA_LD
    issue_chunk128<GUARD>(A, lda, W, nvalid, 0, sA, sB);
    CP_COMMIT();
    int p = 0;
    #pragma unroll
    for (int c = 0; c < 8; c++) {
        if (c < 7) {
            issue_chunk128<GUARD>(A, lda, W, nvalid, (c + 1) * 32,
                                  sA + (p ^ 1) * 128 * TA_LD,
                                  sB + (p ^ 1) * 64 * TA_LD);
            CP_COMMIT();
            CP_WAIT(1);
        } else {
            CP_WAIT(0);
        }
        __syncthreads();
        gl_compute((const uint32_t*)(sA + p * 128 * TA_LD),
                   (const uint32_t*)(sB + p * 64 * TA_LD), acc,
                   warpM, warpN, group, tig);
        __syncthreads();
        p ^= 1;
    }
}

// ---------------------------------------------------------------------------
// Fused second layers + phasor features -> k2/q2 [4096,128].
// grid (32, 4): seg 0=kp->k2 per, 1=qp->q2 per, 2=kh->k2 hyp, 3=qh->q2 hyp
// ---------------------------------------------------------------------------
__global__ void __launch_bounds__(256) layer2_feat(
    const float* __restrict__ hid,
    const float* __restrict__ w0, const float* __restrict__ b0,
    const float* __restrict__ w1, const float* __restrict__ b1,
    const float* __restrict__ w2, const float* __restrict__ b2,
    const float* __restrict__ w3, const float* __restrict__ b3,
    float* __restrict__ k2, float* __restrict__ q2)
{
    cudaGridDependencySynchronize();       // wait for hid (fused1 complete)

    extern __shared__ float smf[];
    const int tid = threadIdx.x, lane = tid & 31, wid = tid >> 5;
    const int group = lane >> 2, tig = lane & 3;
    const int warpM = wid & 3, warpN = wid >> 2;
    const int m0 = blockIdx.x * 128;
    const int seg = blockIdx.y;

    const float* W; const float* Bs;
    if      (seg == 0) { W = w0; Bs = b0; }
    else if (seg == 1) { W = w1; Bs = b1; }
    else if (seg == 2) { W = w2; Bs = b2; }
    else               { W = w3; Bs = b3; }
    const int nseg = (seg < 2) ? 48 : 32;

    float acc[2][4][4] = {};
    tile_mma_pipe<true>(hid + (size_t)m0 * LDH + seg * 256, LDH, W, nseg, smf, acc,
                        warpM, warpN, group, tig);

    cudaTriggerProgrammaticLaunchCompletion();

    float* dst = (seg == 0 || seg == 2) ? k2 : q2;

    if (seg < 2) {
        #pragma unroll
        for (int mf = 0; mf < 2; mf++) {
            int r0 = m0 + warpM * 32 + mf * 16 + group;
            #pragma unroll
            for (int nf = 0; nf < 4; nf++) {
                int colL = warpN * 32 + nf * 8 + 2 * tig;
                #pragma unroll
                for (int e = 0; e < 4; e++) {
                    int n = colL + (e & 1);
                    int m = (e < 2) ? r0 : r0 + 8;
                    if (n < 48) {
                        float ang = tanhf(acc[mf][nf][e] + Bs[n]) * PI_F;
                        float s, c;
                        sincosf(ang, &s, &c);
                        dst[(size_t)m * 128 + n] = c;
                        dst[(size_t)m * 128 + 64 + n] = s;
                    }
                }
            }
        }
    } else {
        #pragma unroll
        for (int mf = 0; mf < 2; mf++) {
            int r0 = m0 + warpM * 32 + mf * 16 + group;
            #pragma unroll
            for (int nf = 0; nf < 4; nf++) {
                int colL = warpN * 32 + nf * 8 + 2 * tig;
                if (colL < 32) {
                    int jj = colL >> 1;
                    float B0 = Bs[colL], B1 = Bs[colL + 1];
                    #pragma unroll
                    for (int h = 0; h < 2; h++) {
                        int m = (h == 0) ? r0 : r0 + 8;
                        float x0 = tanhf(acc[mf][nf][2 * h + 0] + B0) * 0.9f;
                        float y0 = tanhf(acc[mf][nf][2 * h + 1] + B1) * 0.9f;
                        float r = sqrtf(x0 * x0 + y0 * y0);
                        float re, im;
                        if (r > 0.0f) {
                            float sc = (1.0f - r) / r;
                            re = x0 * sc; im = y0 * sc;
                        } else { re = 1.0f; im = 0.0f; }
                        dst[(size_t)m * 128 + 48 + jj] = re;
                        dst[(size_t)m * 128 + 112 + jj] = im;
                    }
                }
            }
        }
    }
}

// ---------------------------------------------------------------------------
// Causal linear attention, single-wave uniform schedule (round-8 proven).
// ---------------------------------------------------------------------------
__constant__ int c_seg[17][2][3] = {
    { {15, 0, 8},  {-1, 0, 0} },
    { {15, 8, 16}, {-1, 0, 0} },
    { {14, 0, 8},  {-1, 0, 0} },
    { {14, 8, 15}, {0, 0, 1} },
    { {13, 0, 8},  {-1, 0, 0} },
    { {13, 8, 14}, {1, 0, 2} },
    { {12, 0, 8},  {-1, 0, 0} },
    { {12, 8, 13}, {2, 0, 3} },
    { {11, 0, 8},  {-1, 0, 0} },
    { {11, 8, 12}, {3, 0, 4} },
    { {10, 0, 8},  {-1, 0, 0} },
    { {10, 8, 11}, {4, 0, 5} },
    { {9, 0, 8},   {-1, 0, 0} },
    { {9, 8, 10},  {5, 0, 6} },
    { {8, 0, 8},   {-1, 0, 0} },
    { {8, 8, 9},   {6, 0, 7} },
    { {7, 0, 8},   {-1, 0, 0} }
};

// floats: sQ[8448] sK0[8448] sK1[8448] sV0[8704] sV1[8704] sS[4352]
#define ATTN_SMEM_U32 (8448 * 3 + 8704 * 2 + 4352)     // 47104
#define ATTN_SMEM_BYTES (ATTN_SMEM_U32 * 4)

__global__ void __launch_bounds__(256) attn_kernel(
    const float* __restrict__ Q2, const float* __restrict__ K2,
    const float* __restrict__ Vb,   // hid + 1024, row stride LDH
    float* __restrict__ ret, float* __restrict__ ret2)
{
    cudaGridDependencySynchronize();       // wait for k2/q2 (layer2 complete)

    extern __shared__ float smf[];
    float* sQ = smf;
    float* sK[2] = { smf + 8448, smf + 16896 };
    float* sV[2] = { smf + 25344, smf + 34048 };
    float* sS = smf + 42752;

    const int tid = threadIdx.x, lane = tid & 31, wid = tid >> 5;
    const int group = lane >> 2, tig = lane & 3;
    const int c0 = blockIdx.y * 128;
    const int b = blockIdx.z;

    const int mS = 32 * (wid >> 2), nS = 16 * (wid & 3);   // S-phase warp tile 32x16
    const int mO = 32 * (wid & 1), nO = 32 * (wid >> 1);   // O-phase warp tile 32x32

    const int lastSeg = (c_seg[blockIdx.x][1][0] >= 0) ? 1 : 0;

    auto issue_kv = [&](int kt, int st) {
        const int kbase = b * 1024 + kt * 64;
        #pragma unroll
        for (int s = 0; s < 8; s++) {
            int slot = tid + s * 256;
            int r = slot >> 5;
            int f = (slot & 31) << 2;
            cpa16(&sK[st][r * 132 + f], &K2[(size_t)(kbase + r) * 128 + f]);
            cpa16(&sV[st][r * 136 + f], &Vb[(size_t)(kbase + r) * LDH + c0 + f]);
        }
    };

    for (int si = 0; si < 2; si++) {
        const int qt = c_seg[blockIdx.x][si][0];
        if (qt < 0) break;
        const int lo = c_seg[blockIdx.x][si][1];
        const int hi = c_seg[blockIdx.x][si][2];
        const int qbase = b * 1024 + qt * 64;

        // load Q tile + first KV tile
        #pragma unroll
        for (int s = 0; s < 8; s++) {
            int slot = tid + s * 256;
            int r = slot >> 5;
            int f = (slot & 31) << 2;
            cpa16(&sQ[r * 132 + f], &Q2[(size_t)(qbase + r) * 128 + f]);
        }
        issue_kv(lo, 0);
        CP_COMMIT();
        CP_WAIT(0);
        __syncthreads();

        float acc[2][4][4];
        #pragma unroll
        for (int mf = 0; mf < 2; mf++)
            #pragma unroll
            for (int nf = 0; nf < 4; nf++)
                #pragma unroll
                for (int e = 0; e < 4; e++) acc[mf][nf][e] = 0.f;

        int p = 0;
        for (int kt = lo; kt < hi; kt++) {
            const bool more = (kt + 1 < hi);
            if (more) {
                issue_kv(kt + 1, p ^ 1);
                CP_COMMIT();
            }

            // S = Qtile @ Ktile^T (64x64)
            const uint32_t* sKu = (const uint32_t*)sK[p];
            const uint32_t* sQu = (const uint32_t*)sQ;
            float sacc[2][2][4];
            #pragma unroll
            for (int mf = 0; mf < 2; mf++)
                #pragma unroll
                for (int nf = 0; nf < 2; nf++)
                    #pragma unroll
                    for (int e = 0; e < 4; e++) sacc[mf][nf][e] = 0.f;

            #pragma unroll
            for (int ks = 0; ks < 16; ks++) {
                int kb = ks * 8;
                uint32_t a[2][4], bb[2][2];
                #pragma unroll
                for (int mf = 0; mf < 2; mf++) {
                    int r0 = mS + mf * 16 + group;
                    a[mf][0] = sQu[r0 * 132 + kb + tig];
                    a[mf][1] = sQu[(r0 + 8) * 132 + kb + tig];
                    a[mf][2] = sQu[r0 * 132 + kb + tig + 4];
                    a[mf][3] = sQu[(r0 + 8) * 132 + kb + tig + 4];
                }
                #pragma unroll
                for (int nf = 0; nf < 2; nf++) {
                    int n0 = nS + nf * 8 + group;
                    bb[nf][0] = sKu[n0 * 132 + kb + tig];
                    bb[nf][1] = sKu[n0 * 132 + kb + tig + 4];
                }
                #pragma unroll
                for (int mf = 0; mf < 2; mf++)
                    #pragma unroll
                    for (int nf = 0; nf < 2; nf++)
                        mma8(sacc[mf][nf], a[mf], bb[nf]);
            }

            // mask diagonal tile (inclusive causal), store S raw bits
            #pragma unroll
            for (int mf = 0; mf < 2; mf++) {
                int row = mS + mf * 16 + group;
                #pragma unroll
                for (int nf = 0; nf < 2; nf++) {
                    int col = nS + nf * 8 + 2 * tig;
                    float s0 = sacc[mf][nf][0], s1 = sacc[mf][nf][1];
                    float s2 = sacc[mf][nf][2], s3 = sacc[mf][nf][3];
                    if (kt == qt) {
                        if (col > row) s0 = 0.f;
                        if (col + 1 > row) s1 = 0.f;
                        if (col > row + 8) s2 = 0.f;
                        if (col + 1 > row + 8) s3 = 0.f;
                    }
                    *(float2*)&sS[row * 68 + col] = make_float2(s0, s1);
                    *(float2*)&sS[(row + 8) * 68 + col] = make_float2(s2, s3);
                }
            }
            __syncthreads();   // sync1: S visible; K[p] reads done

            // O += S @ Vtile (64 x 128)
            const uint32_t* sVu = (const uint32_t*)sV[p];
            const uint32_t* sSu = (const uint32_t*)sS;
            #pragma unroll
            for (int ks = 0; ks < 8; ks++) {
                int kb = ks * 8;
                uint32_t a[2][4], bb[4][2];
                #pragma unroll
                for (int mf = 0; mf < 2; mf++) {
                    int r0 = mO + mf * 16 + group;
                    a[mf][0] = sSu[r0 * 68 + kb + tig];
                    a[mf][1] = sSu[(r0 + 8) * 68 + kb + tig];
                    a[mf][2] = sSu[r0 * 68 + kb + tig + 4];
                    a[mf][3] = sSu[(r0 + 8) * 68 + kb + tig + 4];
                }
                #pragma unroll
                for (int nf = 0; nf < 4; nf++) {
                    int n0 = nO + nf * 8 + group;
                    bb[nf][0] = sVu[(kb + tig) * 136 + n0];
                    bb[nf][1] = sVu[(kb + tig + 4) * 136 + n0];
                }
                #pragma unroll
                for (int mf = 0; mf < 2; mf++)
                    #pragma unroll
                    for (int nf = 0; nf < 4; nf++)
                        mma8(acc[mf][nf], a[mf], bb[nf]);
            }

            if (more) CP_WAIT(0);
            __syncthreads();   // sync2: next stage visible; S/V[p] reads done
            p ^= 1;
        }

        if (si == lastSeg) cudaTriggerProgrammaticLaunchCompletion();

        // epilogue with position scale
        float* dst = (lo == 0) ? ret : ret2;
        #pragma unroll
        for (int mf = 0; mf < 2; mf++) {
            int rl = mO + mf * 16 + group;
            int row = qbase + rl;
            float sc0 = rsqrtf((float)(qt * 64 + rl + 1) * 64.0f);
            float sc1 = rsqrtf((float)(qt * 64 + rl + 9) * 64.0f);
            #pragma unroll
            for (int nf = 0; nf < 4; nf++) {
                int col = c0 + nO + nf * 8 + 2 * tig;
                *(float2*)&dst[(size_t)row * 256 + col] =
                    make_float2(acc[mf][nf][0] * sc0, acc[mf][nf][1] * sc0);
                *(float2*)&dst[(size_t)(row + 8) * 256 + col] =
                    make_float2(acc[mf][nf][2] * sc1, acc[mf][nf][3] * sc1);
            }
        }
    }
}

// ---------------------------------------------------------------------------
// Fast LayerNorm: warp handles TWO rows (doubled MLP). grid 256 x 256 thr.
// (ret already position-scaled; add ret2 for l>=512)
// ---------------------------------------------------------------------------
__global__ void __launch_bounds__(256) ln_kernel(
    const float* __restrict__ ret, const float* __restrict__ ret2,
    const float* __restrict__ g, const float* __restrict__ bta,
    float* __restrict__ rln)
{
    cudaGridDependencySynchronize();       // wait for ret/ret2

    const int wid = threadIdx.x >> 5, lane = threadIdx.x & 31;
    const int row0 = blockIdx.x * 16 + wid * 2;   // rows row0, row0+1

    float4 v[2][2];
    #pragma unroll
    for (int rr = 0; rr < 2; rr++) {              // batch all loads first (MLP)
        int row = row0 + rr;
        const float* p0 = ret + (size_t)row * 256;
        v[rr][0] = *(const float4*)&p0[lane * 8];
        v[rr][1] = *(const float4*)&p0[lane * 8 + 4];
    }
    #pragma unroll
    for (int rr = 0; rr < 2; rr++) {
        int row = row0 + rr;
        if ((row & 1023) >= 512) {
            const float* p1 = ret2 + (size_t)row * 256;
            float4 e = *(const float4*)&p1[lane * 8];
            float4 f = *(const float4*)&p1[lane * 8 + 4];
            v[rr][0].x += e.x; v[rr][0].y += e.y; v[rr][0].z += e.z; v[rr][0].w += e.w;
            v[rr][1].x += f.x; v[rr][1].y += f.y; v[rr][1].z += f.z; v[rr][1].w += f.w;
        }
    }

    cudaTriggerProgrammaticLaunchCompletion();   // gemm_out may roll out

    float4 g0 = *(const float4*)&g[lane * 8];
    float4 g1 = *(const float4*)&g[lane * 8 + 4];
    float4 b0 = *(const float4*)&bta[lane * 8];
    float4 b1 = *(const float4*)&bta[lane * 8 + 4];

    #pragma unroll
    for (int rr = 0; rr < 2; rr++) {
        float4 a = v[rr][0], c = v[rr][1];
        float s = a.x + a.y + a.z + a.w + c.x + c.y + c.z + c.w;
        float s2 = a.x * a.x + a.y * a.y + a.z * a.z + a.w * a.w
                 + c.x * c.x + c.y * c.y + c.z * c.z + c.w * c.w;
        #pragma unroll
        for (int o = 16; o > 0; o >>= 1) {
            s += __shfl_xor_sync(0xFFFFFFFFu, s, o);
            s2 += __shfl_xor_sync(0xFFFFFFFFu, s2, o);
        }
        float mean = s * (1.f / 256.f);
        float var = fmaxf(s2 * (1.f / 256.f) - mean * mean, 0.f);
        float rs = rsqrtf(var + 1e-5f);

        float4 o0, o1;
        o0.x = (a.x - mean) * rs * g0.x + b0.x;
        o0.y = (a.y - mean) * rs * g0.y + b0.y;
        o0.z = (a.z - mean) * rs * g0.z + b0.z;
        o0.w = (a.w - mean) * rs * g0.w + b0.w;
        o1.x = (c.x - mean) * rs * g1.x + b1.x;
        o1.y = (c.y - mean) * rs * g1.y + b1.y;
        o1.z = (c.z - mean) * rs * g1.z + b1.z;
        o1.w = (c.w - mean) * rs * g1.w + b1.w;
        float* po = rln + (size_t)(row0 + rr) * 256;
        *(float4*)&po[lane * 8] = o0;
        *(float4*)&po[lane * 8 + 4] = o1;
    }
}

// ---------------------------------------------------------------------------
// out = x + rln @ out_w^T + out_b.  64x128 tiles, grid (64, 2) = single wave.
// warps: 2(m) x 4(n), warp tile 32x32.
// ---------------------------------------------------------------------------
#define OUT_SMEM_U32 (2 * 64 * TA_LD + 2 * 128 * TA_LD)   // 13824
#define OUT_SMEM_BYTES (OUT_SMEM_U32 * 4)

__global__ void __launch_bounds__(256) gemm_out(
    const float* __restrict__ rln, const float* __restrict__ W,
    const float* __restrict__ Bs, const float* __restrict__ x,
    float* __restrict__ out)
{
    cudaGridDependencySynchronize();       // wait for rln

    extern __shared__ float smf[];
    float* sA = smf;                      // 2 x 64*TA_LD
    float* sB = smf + 2 * 64 * TA_LD;     // 2 x 128*TA_LD
    const int tid = threadIdx.x, lane = tid & 31, wid = tid >> 5;
    const int group = lane >> 2, tig = lane & 3;
    const int warpM = wid & 1, warpN = wid >> 1;
    const int m0 = blockIdx.x * 64;
    const int n0 = blockIdx.y * 128;
    const float* An = rln + (size_t)m0 * 256;
    const float* Wn = W + (size_t)n0 * 256;

    auto issue = [&](int k0, int st) {
        #pragma unroll
        for (int s = 0; s < 2; s++) {          // A: 64 x 32
            int slot = tid + s * 256;
            int r = slot >> 3;
            int kk = (slot & 7) << 2;
            cpa16(&sA[st * 64 * TA_LD + r * TA_LD + kk], &An[(size_t)r * 256 + k0 + kk]);
        }
        #pragma unroll
        for (int s = 0; s < 4; s++) {          // W: 128 x 32
            int slot = tid + s * 256;
            int r = slot >> 3;
            int kk = (slot & 7) << 2;
            cpa16(&sB[st * 128 * TA_LD + r * TA_LD + kk], &Wn[(size_t)r * 256 + k0 + kk]);
        }
    };

    float acc[2][4][4] = {};
    issue(0, 0);
    CP_COMMIT();
    int p = 0;
    #pragma unroll
    for (int c = 0; c < 8; c++) {
        if (c < 7) { issue((c + 1) * 32, p ^ 1); CP_COMMIT(); CP_WAIT(1); }
        else       { CP_WAIT(0); }
        __syncthreads();
        const uint32_t* uA = (const uint32_t*)(sA + p * 64 * TA_LD);
        const uint32_t* uB = (const uint32_t*)(sB + p * 128 * TA_LD);
        #pragma unroll
        for (int ks = 0; ks < 4; ks++) {
            int kb = ks * 8;
            uint32_t a[2][4], b[4][2];
            #pragma unroll
            for (int mf = 0; mf < 2; mf++) {
                int r0 = warpM * 32 + mf * 16 + group;
                a[mf][0] = uA[r0 * TA_LD + kb + tig];
                a[mf][1] = uA[(r0 + 8) * TA_LD + kb + tig];
                a[mf][2] = uA[r0 * TA_LD + kb + tig + 4];
                a[mf][3] = uA[(r0 + 8) * TA_LD + kb + tig + 4];
            }
            #pragma unroll
            for (int nf = 0; nf < 4; nf++) {
                int nn = warpN * 32 + nf * 8 + group;
                b[nf][0] = uB[nn * TA_LD + kb + tig];
                b[nf][1] = uB[nn * TA_LD + kb + tig + 4];
            }
            #pragma unroll
            for (int mf = 0; mf < 2; mf++)
                #pragma unroll
                for (int nf = 0; nf < 4; nf++)
                    mma8(acc[mf][nf], a[mf], b[nf]);
        }
        __syncthreads();
        p ^= 1;
    }

    #pragma unroll
    for (int mf = 0; mf < 2; mf++) {
        int r0 = m0 + warpM * 32 + mf * 16 + group;
        #pragma unroll
        for (int nf = 0; nf < 4; nf++) {
            int n = n0 + warpN * 32 + nf * 8 + 2 * tig;
            float bv0 = Bs[n], bv1 = Bs[n + 1];
            float2 x0 = *(const float2*)&x[(size_t)r0 * 256 + n];
            float2 x1 = *(const float2*)&x[(size_t)(r0 + 8) * 256 + n];
            *(float2*)&out[(size_t)r0 * 256 + n] =
                make_float2(acc[mf][nf][0] + bv0 + x0.x, acc[mf][nf][1] + bv1 + x0.y);
            *(float2*)&out[(size_t)(r0 + 8) * 256 + n] =
                make_float2(acc[mf][nf][2] + bv0 + x1.x, acc[mf][nf][3] + bv1 + x1.y);
        }
    }
}

// ---------------------------------------------------------------------------
extern "C" void kernel_launch(void* const* d_in, const int* in_sizes, int n_in,
                              void* d_out, int out_size)
{
    (void)in_sizes; (void)n_in; (void)out_size;
    const float* x     = (const float*)d_in[0];
    const float* kp_w1 = (const float*)d_in[1];
    const float* kp_b1 = (const float*)d_in[2];
    const float* kp_w2 = (const float*)d_in[3];
    const float* kp_b2 = (const float*)d_in[4];
    const float* qp_w1 = (const float*)d_in[5];
    const float* qp_b1 = (const float*)d_in[6];
    const float* qp_w2 = (const float*)d_in[7];
    const float* qp_b2 = (const float*)d_in[8];
    const float* kh_w1 = (const float*)d_in[9];
    const float* kh_b1 = (const float*)d_in[10];
    const float* kh_w2 = (const float*)d_in[11];
    const float* kh_b2 = (const float*)d_in[12];
    const float* qh_w1 = (const float*)d_in[13];
    const float* qh_b1 = (const float*)d_in[14];
    const float* qh_w2 = (const float*)d_in[15];
    const float* qh_b2 = (const float*)d_in[16];
    const float* v_w   = (const float*)d_in[17];
    const float* v_b   = (const float*)d_in[18];
    const float* ln_g  = (const float*)d_in[19];
    const float* ln_b  = (const float*)d_in[20];
    const float* out_w = (const float*)d_in[21];
    const float* out_b = (const float*)d_in[22];
    float* out = (float*)d_out;

    float *hid, *k2, *q2, *ret, *ret2, *rln;
    cudaGetSymbolAddress((void**)&hid, g_hid);
    cudaGetSymbolAddress((void**)&k2, g_k2);
    cudaGetSymbolAddress((void**)&q2, g_q2);
    cudaGetSymbolAddress((void**)&ret, g_ret);
    cudaGetSymbolAddress((void**)&ret2, g_ret2);
    cudaGetSymbolAddress((void**)&rln, g_rln);

    static bool attr_set = false;
    if (!attr_set) {
        cudaFuncSetAttribute(gemm_fused1, cudaFuncAttributeMaxDynamicSharedMemorySize,
                             F1_SMEM_BYTES);
        cudaFuncSetAttribute(layer2_feat, cudaFuncAttributeMaxDynamicSharedMemorySize,
                             GEMM_SMEM_BYTES);
        cudaFuncSetAttribute(attn_kernel, cudaFuncAttributeMaxDynamicSharedMemorySize,
                             ATTN_SMEM_BYTES);
        cudaFuncSetAttribute(gemm_out, cudaFuncAttributeMaxDynamicSharedMemorySize,
                             OUT_SMEM_BYTES);
        attr_set = true;
    }

    cudaLaunchAttribute pdl;
    pdl.id = cudaLaunchAttributeProgrammaticStreamSerialization;
    pdl.val.programmaticStreamSerializationAllowed = 1;

    // 1. fused first layers + V projection (plain launch)
    gemm_fused1<<<dim3(32, 10), 256, F1_SMEM_BYTES>>>(
        x, kp_w1, kp_b1, qp_w1, qp_b1, kh_w1, kh_b1, qh_w1, qh_b1, v_w, v_b, hid);

    // 2. fused second layers -> phasor features (PDL consumer)
    {
        cudaLaunchConfig_t cfg = {};
        cfg.gridDim = dim3(32, 4); cfg.blockDim = dim3(256);
        cfg.dynamicSmemBytes = GEMM_SMEM_BYTES; cfg.stream = 0;
        cfg.attrs = &pdl; cfg.numAttrs = 1;
        cudaLaunchKernelEx(&cfg, layer2_feat,
                           (const float*)hid, kp_w2, kp_b2, qp_w2, qp_b2,
                           kh_w2, kh_b2, qh_w2, qh_b2, k2, q2);
    }

    // 3. causal linear attention (PDL consumer)
    {
        cudaLaunchConfig_t cfg = {};
        cfg.gridDim = dim3(17, 2, 4); cfg.blockDim = dim3(256);
        cfg.dynamicSmemBytes = ATTN_SMEM_BYTES; cfg.stream = 0;
        cfg.attrs = &pdl; cfg.numAttrs = 1;
        cudaLaunchKernelEx(&cfg, attn_kernel,
                           (const float*)q2, (const float*)k2,
                           (const float*)(hid + 1024), ret, ret2);
    }

    // 4. fast LayerNorm (PDL consumer)
    {
        cudaLaunchConfig_t cfg = {};
        cfg.gridDim = dim3(256); cfg.blockDim = dim3(256);
        cfg.dynamicSmemBytes = 0; cfg.stream = 0;
        cfg.attrs = &pdl; cfg.numAttrs = 1;
        cudaLaunchKernelEx(&cfg, ln_kernel,
                           (const float*)ret, (const float*)ret2, ln_g, ln_b, rln);
    }

    // 5. output projection + residual (PDL consumer)
    {
        cudaLaunchConfig_t cfg = {};
        cfg.gridDim = dim3(64, 2); cfg.blockDim = dim3(256);
        cfg.dynamicSmemBytes = OUT_SMEM_BYTES; cfg.stream = 0;
        cfg.attrs = &pdl; cfg.numAttrs = 1;
        cudaLaunchKernelEx(&cfg, gemm_out,
                           (const float*)rln, out_w, out_b, x, out);
    }
}

// round 15
// speedup vs baseline: 1.1129x; 1.1129x over previous
#include <cuda_runtime.h>
#include <math.h>
#include <stdint.h>

// B=4, L=1024, D=256, N_PER=48, N_HYP=16, K=64, features 2K=128
#define M_ROWS 4096
#define LDH 1280
#define PI_F 3.14159265358979323846f
#define TA_LD 36   // smem k-chunk stride (36 mod 32 = 4 -> conflict-free frags)

// scratch
__device__ float g_hid[M_ROWS * LDH];   // [GELU(kp|qp|kh|qh hidden) | V]
__device__ float g_k2[M_ROWS * 128];
__device__ float g_q2[M_ROWS * 128];
__device__ float g_ret[M_ROWS * 256];
__device__ float g_ret2[M_ROWS * 256];
__device__ float g_rln[M_ROWS * 256];

__device__ __forceinline__ float gelu_exact(float v) {
    return 0.5f * v * (1.0f + erff(v * 0.7071067811865475f));
}

// ---- cp.async helpers -----------------------------------------------------
__device__ __forceinline__ void cpa16(void* s, const void* g) {
    uint32_t sa = (uint32_t)__cvta_generic_to_shared(s);
    asm volatile("cp.async.cg.shared.global [%0], [%1], 16;" :: "r"(sa), "l"(g));
}
__device__ __forceinline__ void cpa16z(void* s, const void* g, int sz) {
    uint32_t sa = (uint32_t)__cvta_generic_to_shared(s);
    asm volatile("cp.async.cg.shared.global [%0], [%1], 16, %2;" :: "r"(sa), "l"(g), "r"(sz));
}
#define CP_COMMIT() asm volatile("cp.async.commit_group;" ::: "memory")
#define CP_WAIT(N)  asm volatile("cp.async.wait_group %0;" :: "n"(N) : "memory")

// raw fp32 bits fed to mma.tf32 (HW truncates to tf32)
__device__ __forceinline__ void mma8(float c[4], const uint32_t a[4], const uint32_t b[2]) {
    asm("mma.sync.aligned.m16n8k8.row.col.f32.tf32.tf32.f32 "
        "{%0,%1,%2,%3},{%4,%5,%6,%7},{%8,%9},{%0,%1,%2,%3};"
        : "+f"(c[0]), "+f"(c[1]), "+f"(c[2]), "+f"(c[3])
        : "r"(a[0]), "r"(a[1]), "r"(a[2]), "r"(a[3]), "r"(b[0]), "r"(b[1]));
}

// ===========================================================================
// Fused first layers: hid[4096,1280] = [GELU(x@W1^T+b1) x4 | x@v_w^T+v_b]
// 128x128 tiles, 2-stage pipe. grid (32, 10). warps 2(m) x 4(n).
// ===========================================================================
#define F1_SMEM_U32 (2 * 128 * TA_LD + 2 * 128 * TA_LD)   // 18432
#define F1_SMEM_BYTES (F1_SMEM_U32 * 4)                   // 73728

__global__ void __launch_bounds__(256) gemm_fused1(
    const float* __restrict__ x,
    const float* __restrict__ w0, const float* __restrict__ b0,
    const float* __restrict__ w1, const float* __restrict__ b1,
    const float* __restrict__ w2, const float* __restrict__ b2,
    const float* __restrict__ w3, const float* __restrict__ b3,
    const float* __restrict__ w4, const float* __restrict__ b4,
    float* __restrict__ hid)
{
    extern __shared__ float smf[];
    float* sA = smf;                        // 2 x 128*TA_LD
    float* sB = smf + 2 * 128 * TA_LD;      // 2 x 128*TA_LD
    const int tid = threadIdx.x, lane = tid & 31, wid = tid >> 5;
    const int group = lane >> 2, tig = lane & 3;
    const int warpM = wid & 1, warpN = wid >> 1;
    const int m0 = blockIdx.x * 128;
    const int by = blockIdx.y;
    const int seg = by >> 1;
    const int half = by & 1;

    const float* W; const float* Bs;
    if      (seg == 0) { W = w0; Bs = b0; }
    else if (seg == 1) { W = w1; Bs = b1; }
    else if (seg == 2) { W = w2; Bs = b2; }
    else if (seg == 3) { W = w3; Bs = b3; }
    else               { W = w4; Bs = b4; }
    W += (size_t)(half * 128) * 256;
    Bs += half * 128;
    const float* An = x + (size_t)m0 * 256;

    auto issue = [&](int k0, int st) {
        #pragma unroll
        for (int s = 0; s < 4; s++) {           // A: 128 x 32
            int slot = tid + s * 256;
            int r = slot >> 3;
            int kk = (slot & 7) << 2;
            cpa16(&sA[st * 128 * TA_LD + r * TA_LD + kk],
                  &An[(size_t)r * 256 + k0 + kk]);
        }
        #pragma unroll
        for (int s = 0; s < 4; s++) {           // W: 128 x 32
            int slot = tid + s * 256;
            int r = slot >> 3;
            int kk = (slot & 7) << 2;
            cpa16(&sB[st * 128 * TA_LD + r * TA_LD + kk],
                  &W[(size_t)r * 256 + k0 + kk]);
        }
    };

    float acc[4][4][4] = {};
    issue(0, 0);
    CP_COMMIT();
    int p = 0;
    #pragma unroll
    for (int c = 0; c < 8; c++) {
        if (c < 7) { issue((c + 1) * 32, p ^ 1); CP_COMMIT(); CP_WAIT(1); }
        else       { CP_WAIT(0); }
        __syncthreads();
        const uint32_t* uA = (const uint32_t*)(sA + p * 128 * TA_LD);
        const uint32_t* uB = (const uint32_t*)(sB + p * 128 * TA_LD);
        #pragma unroll
        for (int ks = 0; ks < 4; ks++) {
            int kb = ks * 8;
            uint32_t a[4][4], b[4][2];
            #pragma unroll
            for (int mf = 0; mf < 4; mf++) {
                int r0 = warpM * 64 + mf * 16 + group;
                a[mf][0] = uA[r0 * TA_LD + kb + tig];
                a[mf][1] = uA[(r0 + 8) * TA_LD + kb + tig];
                a[mf][2] = uA[r0 * TA_LD + kb + tig + 4];
                a[mf][3] = uA[(r0 + 8) * TA_LD + kb + tig + 4];
            }
            #pragma unroll
            for (int nf = 0; nf < 4; nf++) {
                int n0 = warpN * 32 + nf * 8 + group;
                b[nf][0] = uB[n0 * TA_LD + kb + tig];
                b[nf][1] = uB[n0 * TA_LD + kb + tig + 4];
            }
            #pragma unroll
            for (int mf = 0; mf < 4; mf++)
                #pragma unroll
                for (int nf = 0; nf < 4; nf++)
                    mma8(acc[mf][nf], a[mf], b[nf]);
        }
        __syncthreads();
        p ^= 1;
    }

    #pragma unroll
    for (int mf = 0; mf < 4; mf++) {
        int r0 = m0 + warpM * 64 + mf * 16 + group;
        #pragma unroll
        for (int nf = 0; nf < 4; nf++) {
            int colL = warpN * 32 + nf * 8 + 2 * tig;
            float bv0 = Bs[colL], bv1 = Bs[colL + 1];
            float v00 = acc[mf][nf][0] + bv0, v01 = acc[mf][nf][1] + bv1;
            float v10 = acc[mf][nf][2] + bv0, v11 = acc[mf][nf][3] + bv1;
            if (seg < 4) {
                v00 = gelu_exact(v00); v01 = gelu_exact(v01);
                v10 = gelu_exact(v10); v11 = gelu_exact(v11);
            }
            int gcol = by * 128 + colL;
            *(float2*)&hid[(size_t)r0 * LDH + gcol] = make_float2(v00, v01);
            *(float2*)&hid[(size_t)(r0 + 8) * LDH + gcol] = make_float2(v10, v11);
        }
    }
}

// ===========================================================================
// 128x64 tile engine (cp.async pipelined, 2-stage) — used by layer2_feat
// ===========================================================================
template <bool GUARD>
__device__ __forceinline__ void issue_chunk128(
    const float* __restrict__ A, int lda,
    const float* __restrict__ W, int nvalid, int k0,
    float* sA, float* sB)
{
    const int tid = threadIdx.x;
    #pragma unroll
    for (int s = 0; s < 4; s++) {                 // A: 128 x 32
        int slot = tid + s * 256;
        int r = slot >> 3;
        int kk = (slot & 7) << 2;
        cpa16(&sA[r * TA_LD + kk], &A[(size_t)r * lda + k0 + kk]);
    }
    #pragma unroll
    for (int s = 0; s < 2; s++) {                 // W: 64 x 32
        int slot = tid + s * 256;
        int r = slot >> 3;
        int kk = (slot & 7) << 2;
        if (GUARD) {
            int rr = (r < nvalid) ? r : 0;
            cpa16z(&sB[r * TA_LD + kk], &W[(size_t)rr * 256 + k0 + kk],
                   (r < nvalid) ? 16 : 0);
        } else {
            cpa16(&sB[r * TA_LD + kk], &W[(size_t)r * 256 + k0 + kk]);
        }
    }
}

__device__ __forceinline__ void gl_compute(
    const uint32_t* sA, const uint32_t* sB, float acc[2][4][4],
    int warpM, int warpN, int group, int tig)
{
    #pragma unroll
    for (int ks = 0; ks < 4; ks++) {
        int kb = ks * 8;
        uint32_t a[2][4], b[4][2];
        #pragma unroll
        for (int mf = 0; mf < 2; mf++) {
            int r0 = warpM * 32 + mf * 16 + group;
            a[mf][0] = sA[r0 * TA_LD + kb + tig];
            a[mf][1] = sA[(r0 + 8) * TA_LD + kb + tig];
            a[mf][2] = sA[r0 * TA_LD + kb + tig + 4];
            a[mf][3] = sA[(r0 + 8) * TA_LD + kb + tig + 4];
        }
        #pragma unroll
        for (int nf = 0; nf < 4; nf++) {
            int n0 = warpN * 32 + nf * 8 + group;
            b[nf][0] = sB[n0 * TA_LD + kb + tig];
            b[nf][1] = sB[n0 * TA_LD + kb + tig + 4];
        }
        #pragma unroll
        for (int mf = 0; mf < 2; mf++)
            #pragma unroll
            for (int nf = 0; nf < 4; nf++)
                mma8(acc[mf][nf], a[mf], b[nf]);
    }
}

#define GEMM_SMEM_U32 (2 * 128 * TA_LD + 2 * 64 * TA_LD)   // 13824
#define GEMM_SMEM_BYTES (GEMM_SMEM_U32 * 4)

template <bool GUARD>
__device__ __forceinline__ void tile_mma_pipe(
    const float* __restrict__ A, int lda,
    const float* __restrict__ W, int nvalid,
    float* smf, float acc[2][4][4],
    int warpM, int warpN, int group, int tig)
{
    float* sA = smf;                       // 2 x 128*TA_LD
    float* sB = smf + 2 * 128 * TA_LD;     // 2 x 64*TA_LD
    issue_chunk128<GUARD>(A, lda, W, nvalid, 0, sA, sB);
    CP_COMMIT();
    int p = 0;
    #pragma unroll
    for (int c = 0; c < 8; c++) {
        if (c < 7) {
            issue_chunk128<GUARD>(A, lda, W, nvalid, (c + 1) * 32,
                                  sA + (p ^ 1) * 128 * TA_LD,
                                  sB + (p ^ 1) * 64 * TA_LD);
            CP_COMMIT();
            CP_WAIT(1);
        } else {
            CP_WAIT(0);
        }
        __syncthreads();
        gl_compute((const uint32_t*)(sA + p * 128 * TA_LD),
                   (const uint32_t*)(sB + p * 64 * TA_LD), acc,
                   warpM, warpN, group, tig);
        __syncthreads();
        p ^= 1;
    }
}

// ---------------------------------------------------------------------------
// Fused second layers + phasor features -> k2/q2 [4096,128].
// grid (32, 4): seg 0=kp->k2 per, 1=qp->q2 per, 2=kh->k2 hyp, 3=qh->q2 hyp
// ---------------------------------------------------------------------------
__global__ void __launch_bounds__(256) layer2_feat(
    const float* __restrict__ hid,
    const float* __restrict__ w0, const float* __restrict__ b0,
    const float* __restrict__ w1, const float* __restrict__ b1,
    const float* __restrict__ w2, const float* __restrict__ b2,
    const float* __restrict__ w3, const float* __restrict__ b3,
    float* __restrict__ k2, float* __restrict__ q2)
{
    extern __shared__ float smf[];
    const int tid = threadIdx.x, lane = tid & 31, wid = tid >> 5;
    const int group = lane >> 2, tig = lane & 3;
    const int warpM = wid & 3, warpN = wid >> 2;
    const int m0 = blockIdx.x * 128;
    const int seg = blockIdx.y;

    const float* W; const float* Bs;
    if      (seg == 0) { W = w0; Bs = b0; }
    else if (seg == 1) { W = w1; Bs = b1; }
    else if (seg == 2) { W = w2; Bs = b2; }
    else               { W = w3; Bs = b3; }
    const int nseg = (seg < 2) ? 48 : 32;

    float acc[2][4][4] = {};
    tile_mma_pipe<true>(hid + (size_t)m0 * LDH + seg * 256, LDH, W, nseg, smf, acc,
                        warpM, warpN, group, tig);

    float* dst = (seg == 0 || seg == 2) ? k2 : q2;

    if (seg < 2) {
        #pragma unroll
        for (int mf = 0; mf < 2; mf++) {
            int r0 = m0 + warpM * 32 + mf * 16 + group;
            #pragma unroll
            for (int nf = 0; nf < 4; nf++) {
                int colL = warpN * 32 + nf * 8 + 2 * tig;
                #pragma unroll
                for (int e = 0; e < 4; e++) {
                    int n = colL + (e & 1);
                    int m = (e < 2) ? r0 : r0 + 8;
                    if (n < 48) {
                        float ang = tanhf(acc[mf][nf][e] + Bs[n]) * PI_F;
                        float s, c;
                        sincosf(ang, &s, &c);
                        dst[(size_t)m * 128 + n] = c;
                        dst[(size_t)m * 128 + 64 + n] = s;
                    }
                }
            }
        }
    } else {
        #pragma unroll
        for (int mf = 0; mf < 2; mf++) {
            int r0 = m0 + warpM * 32 + mf * 16 + group;
            #pragma unroll
            for (int nf = 0; nf < 4; nf++) {
                int colL = warpN * 32 + nf * 8 + 2 * tig;
                if (colL < 32) {
                    int jj = colL >> 1;
                    float B0 = Bs[colL], B1 = Bs[colL + 1];
                    #pragma unroll
                    for (int h = 0; h < 2; h++) {
                        int m = (h == 0) ? r0 : r0 + 8;
                        float x0 = tanhf(acc[mf][nf][2 * h + 0] + B0) * 0.9f;
                        float y0 = tanhf(acc[mf][nf][2 * h + 1] + B1) * 0.9f;
                        float r = sqrtf(x0 * x0 + y0 * y0);
                        float re, im;
                        if (r > 0.0f) {
                            float sc = (1.0f - r) / r;
                            re = x0 * sc; im = y0 * sc;
                        } else { re = 1.0f; im = 0.0f; }
                        dst[(size_t)m * 128 + 48 + jj] = re;
                        dst[(size_t)m * 128 + 112 + jj] = im;
                    }
                }
            }
        }
    }
}

// ---------------------------------------------------------------------------
// Causal linear attention, single-wave uniform schedule (round-8 proven).
// ---------------------------------------------------------------------------
__constant__ int c_seg[17][2][3] = {
    { {15, 0, 8},  {-1, 0, 0} },
    { {15, 8, 16}, {-1, 0, 0} },
    { {14, 0, 8},  {-1, 0, 0} },
    { {14, 8, 15}, {0, 0, 1} },
    { {13, 0, 8},  {-1, 0, 0} },
    { {13, 8, 14}, {1, 0, 2} },
    { {12, 0, 8},  {-1, 0, 0} },
    { {12, 8, 13}, {2, 0, 3} },
    { {11, 0, 8},  {-1, 0, 0} },
    { {11, 8, 12}, {3, 0, 4} },
    { {10, 0, 8},  {-1, 0, 0} },
    { {10, 8, 11}, {4, 0, 5} },
    { {9, 0, 8},   {-1, 0, 0} },
    { {9, 8, 10},  {5, 0, 6} },
    { {8, 0, 8},   {-1, 0, 0} },
    { {8, 8, 9},   {6, 0, 7} },
    { {7, 0, 8},   {-1, 0, 0} }
};

// floats: sQ[8448] sK0[8448] sK1[8448] sV0[8704] sV1[8704] sS[4352]
#define ATTN_SMEM_U32 (8448 * 3 + 8704 * 2 + 4352)     // 47104
#define ATTN_SMEM_BYTES (ATTN_SMEM_U32 * 4)

__global__ void __launch_bounds__(256) attn_kernel(
    const float* __restrict__ Q2, const float* __restrict__ K2,
    const float* __restrict__ Vb,   // hid + 1024, row stride LDH
    float* __restrict__ ret, float* __restrict__ ret2)
{
    extern __shared__ float smf[];
    float* sQ = smf;
    float* sK[2] = { smf + 8448, smf + 16896 };
    float* sV[2] = { smf + 25344, smf + 34048 };
    float* sS = smf + 42752;

    const int tid = threadIdx.x, lane = tid & 31, wid = tid >> 5;
    const int group = lane >> 2, tig = lane & 3;
    const int c0 = blockIdx.y * 128;
    const int b = blockIdx.z;

    const int mS = 32 * (wid >> 2), nS = 16 * (wid & 3);   // S-phase warp tile 32x16
    const int mO = 32 * (wid & 1), nO = 32 * (wid >> 1);   // O-phase warp tile 32x32

    auto issue_kv = [&](int kt, int st) {
        const int kbase = b * 1024 + kt * 64;
        #pragma unroll
        for (int s = 0; s < 8; s++) {
            int slot = tid + s * 256;
            int r = slot >> 5;
            int f = (slot & 31) << 2;
            cpa16(&sK[st][r * 132 + f], &K2[(size_t)(kbase + r) * 128 + f]);
            cpa16(&sV[st][r * 136 + f], &Vb[(size_t)(kbase + r) * LDH + c0 + f]);
        }
    };

    for (int si = 0; si < 2; si++) {
        const int qt = c_seg[blockIdx.x][si][0];
        if (qt < 0) break;
        const int lo = c_seg[blockIdx.x][si][1];
        const int hi = c_seg[blockIdx.x][si][2];
        const int qbase = b * 1024 + qt * 64;

        // load Q tile + first KV tile
        #pragma unroll
        for (int s = 0; s < 8; s++) {
            int slot = tid + s * 256;
            int r = slot >> 5;
            int f = (slot & 31) << 2;
            cpa16(&sQ[r * 132 + f], &Q2[(size_t)(qbase + r) * 128 + f]);
        }
        issue_kv(lo, 0);
        CP_COMMIT();
        CP_WAIT(0);
        __syncthreads();

        float acc[2][4][4];
        #pragma unroll
        for (int mf = 0; mf < 2; mf++)
            #pragma unroll
            for (int nf = 0; nf < 4; nf++)
                #pragma unroll
                for (int e = 0; e < 4; e++) acc[mf][nf][e] = 0.f;

        int p = 0;
        for (int kt = lo; kt < hi; kt++) {
            const bool more = (kt + 1 < hi);
            if (more) {
                issue_kv(kt + 1, p ^ 1);
                CP_COMMIT();
            }

            // S = Qtile @ Ktile^T (64x64)
            const uint32_t* sKu = (const uint32_t*)sK[p];
            const uint32_t* sQu = (const uint32_t*)sQ;
            float sacc[2][2][4];
            #pragma unroll
            for (int mf = 0; mf < 2; mf++)
                #pragma unroll
                for (int nf = 0; nf < 2; nf++)
                    #pragma unroll
                    for (int e = 0; e < 4; e++) sacc[mf][nf][e] = 0.f;

            #pragma unroll
            for (int ks = 0; ks < 16; ks++) {
                int kb = ks * 8;
                uint32_t a[2][4], bb[2][2];
                #pragma unroll
                for (int mf = 0; mf < 2; mf++) {
                    int r0 = mS + mf * 16 + group;
                    a[mf][0] = sQu[r0 * 132 + kb + tig];
                    a[mf][1] = sQu[(r0 + 8) * 132 + kb + tig];
                    a[mf][2] = sQu[r0 * 132 + kb + tig + 4];
                    a[mf][3] = sQu[(r0 + 8) * 132 + kb + tig + 4];
                }
                #pragma unroll
                for (int nf = 0; nf < 2; nf++) {
                    int n0 = nS + nf * 8 + group;
                    bb[nf][0] = sKu[n0 * 132 + kb + tig];
                    bb[nf][1] = sKu[n0 * 132 + kb + tig + 4];
                }
                #pragma unroll
                for (int mf = 0; mf < 2; mf++)
                    #pragma unroll
                    for (int nf = 0; nf < 2; nf++)
                        mma8(sacc[mf][nf], a[mf], bb[nf]);
            }

            // mask diagonal tile (inclusive causal), store S raw bits
            #pragma unroll
            for (int mf = 0; mf < 2; mf++) {
                int row = mS + mf * 16 + group;
                #pragma unroll
                for (int nf = 0; nf < 2; nf++) {
                    int col = nS + nf * 8 + 2 * tig;
                    float s0 = sacc[mf][nf][0], s1 = sacc[mf][nf][1];
                    float s2 = sacc[mf][nf][2], s3 = sacc[mf][nf][3];
                    if (kt == qt) {
                        if (col > row) s0 = 0.f;
                        if (col + 1 > row) s1 = 0.f;
                        if (col > row + 8) s2 = 0.f;
                        if (col + 1 > row + 8) s3 = 0.f;
                    }
                    *(float2*)&sS[row * 68 + col] = make_float2(s0, s1);
                    *(float2*)&sS[(row + 8) * 68 + col] = make_float2(s2, s3);
                }
            }
            __syncthreads();   // sync1: S visible; K[p] reads done

            // O += S @ Vtile (64 x 128)
            const uint32_t* sVu = (const uint32_t*)sV[p];
            const uint32_t* sSu = (const uint32_t*)sS;
            #pragma unroll
            for (int ks = 0; ks < 8; ks++) {
                int kb = ks * 8;
                uint32_t a[2][4], bb[4][2];
                #pragma unroll
                for (int mf = 0; mf < 2; mf++) {
                    int r0 = mO + mf * 16 + group;
                    a[mf][0] = sSu[r0 * 68 + kb + tig];
                    a[mf][1] = sSu[(r0 + 8) * 68 + kb + tig];
                    a[mf][2] = sSu[r0 * 68 + kb + tig + 4];
                    a[mf][3] = sSu[(r0 + 8) * 68 + kb + tig + 4];
                }
                #pragma unroll
                for (int nf = 0; nf < 4; nf++) {
                    int n0 = nO + nf * 8 + group;
                    bb[nf][0] = sVu[(kb + tig) * 136 + n0];
                    bb[nf][1] = sVu[(kb + tig + 4) * 136 + n0];
                }
                #pragma unroll
                for (int mf = 0; mf < 2; mf++)
                    #pragma unroll
                    for (int nf = 0; nf < 4; nf++)
                        mma8(acc[mf][nf], a[mf], bb[nf]);
            }

            if (more) CP_WAIT(0);
            __syncthreads();   // sync2: next stage visible; S/V[p] reads done
            p ^= 1;
        }

        // epilogue with position scale
        float* dst = (lo == 0) ? ret : ret2;
        #pragma unroll
        for (int mf = 0; mf < 2; mf++) {
            int rl = mO + mf * 16 + group;
            int row = qbase + rl;
            float sc0 = rsqrtf((float)(qt * 64 + rl + 1) * 64.0f);
            float sc1 = rsqrtf((float)(qt * 64 + rl + 9) * 64.0f);
            #pragma unroll
            for (int nf = 0; nf < 4; nf++) {
                int col = c0 + nO + nf * 8 + 2 * tig;
                *(float2*)&dst[(size_t)row * 256 + col] =
                    make_float2(acc[mf][nf][0] * sc0, acc[mf][nf][1] * sc0);
                *(float2*)&dst[(size_t)(row + 8) * 256 + col] =
                    make_float2(acc[mf][nf][2] * sc1, acc[mf][nf][3] * sc1);
            }
        }
    }
}

// ---------------------------------------------------------------------------
// Fast LayerNorm: warp handles TWO rows (doubled MLP). grid 256 x 256 thr.
// (ret already position-scaled; add ret2 for l>=512)
// ---------------------------------------------------------------------------
__global__ void __launch_bounds__(256) ln_kernel(
    const float* __restrict__ ret, const float* __restrict__ ret2,
    const float* __restrict__ g, const float* __restrict__ bta,
    float* __restrict__ rln)
{
    const int wid = threadIdx.x >> 5, lane = threadIdx.x & 31;
    const int row0 = blockIdx.x * 16 + wid * 2;   // rows row0, row0+1

    float4 v[2][2];
    #pragma unroll
    for (int rr = 0; rr < 2; rr++) {              // batch all loads first (MLP)
        int row = row0 + rr;
        const float* p0 = ret + (size_t)row * 256;
        v[rr][0] = *(const float4*)&p0[lane * 8];
        v[rr][1] = *(const float4*)&p0[lane * 8 + 4];
    }
    #pragma unroll
    for (int rr = 0; rr < 2; rr++) {
        int row = row0 + rr;
        if ((row & 1023) >= 512) {
            const float* p1 = ret2 + (size_t)row * 256;
            float4 e = *(const float4*)&p1[lane * 8];
            float4 f = *(const float4*)&p1[lane * 8 + 4];
            v[rr][0].x += e.x; v[rr][0].y += e.y; v[rr][0].z += e.z; v[rr][0].w += e.w;
            v[rr][1].x += f.x; v[rr][1].y += f.y; v[rr][1].z += f.z; v[rr][1].w += f.w;
        }
    }

    float4 g0 = *(const float4*)&g[lane * 8];
    float4 g1 = *(const float4*)&g[lane * 8 + 4];
    float4 b0 = *(const float4*)&bta[lane * 8];
    float4 b1 = *(const float4*)&bta[lane * 8 + 4];

    #pragma unroll
    for (int rr = 0; rr < 2; rr++) {
        float4 a = v[rr][0], c = v[rr][1];
        float s = a.x + a.y + a.z + a.w + c.x + c.y + c.z + c.w;
        float s2 = a.x * a.x + a.y * a.y + a.z * a.z + a.w * a.w
                 + c.x * c.x + c.y * c.y + c.z * c.z + c.w * c.w;
        #pragma unroll
        for (int o = 16; o > 0; o >>= 1) {
            s += __shfl_xor_sync(0xFFFFFFFFu, s, o);
            s2 += __shfl_xor_sync(0xFFFFFFFFu, s2, o);
        }
        float mean = s * (1.f / 256.f);
        float var = fmaxf(s2 * (1.f / 256.f) - mean * mean, 0.f);
        float rs = rsqrtf(var + 1e-5f);

        float4 o0, o1;
        o0.x = (a.x - mean) * rs * g0.x + b0.x;
        o0.y = (a.y - mean) * rs * g0.y + b0.y;
        o0.z = (a.z - mean) * rs * g0.z + b0.z;
        o0.w = (a.w - mean) * rs * g0.w + b0.w;
        o1.x = (c.x - mean) * rs * g1.x + b1.x;
        o1.y = (c.y - mean) * rs * g1.y + b1.y;
        o1.z = (c.z - mean) * rs * g1.z + b1.z;
        o1.w = (c.w - mean) * rs * g1.w + b1.w;
        float* po = rln + (size_t)(row0 + rr) * 256;
        *(float4*)&po[lane * 8] = o0;
        *(float4*)&po[lane * 8 + 4] = o1;
    }
}

// ---------------------------------------------------------------------------
// out = x + rln @ out_w^T + out_b.  64x128 tiles, grid (64, 2) = single wave.
// Residual x tile prefetched into smem via an early cp.async group so the
// epilogue reads smem instead of paying exposed DRAM latency at the tail.
// ---------------------------------------------------------------------------
#define OUT_PIPE_U32 (2 * 64 * TA_LD + 2 * 128 * TA_LD)   // 13824
#define OUT_SMEM_U32 (OUT_PIPE_U32 + 64 * 128)            // + 8192 = 22016
#define OUT_SMEM_BYTES (OUT_SMEM_U32 * 4)                 // 88064

__global__ void __launch_bounds__(256) gemm_out(
    const float* __restrict__ rln, const float* __restrict__ W,
    const float* __restrict__ Bs, const float* __restrict__ x,
    float* __restrict__ out)
{
    extern __shared__ float smf[];
    float* sA = smf;                      // 2 x 64*TA_LD
    float* sB = smf + 2 * 64 * TA_LD;     // 2 x 128*TA_LD
    float* sX = smf + OUT_PIPE_U32;       // 64 x 128 residual tile
    const int tid = threadIdx.x, lane = tid & 31, wid = tid >> 5;
    const int group = lane >> 2, tig = lane & 3;
    const int warpM = wid & 1, warpN = wid >> 1;
    const int m0 = blockIdx.x * 64;
    const int n0 = blockIdx.y * 128;
    const float* An = rln + (size_t)m0 * 256;
    const float* Wn = W + (size_t)n0 * 256;

    // residual prefetch: 64x128 floats, 2 cpa16 per thread, own (oldest) group
    #pragma unroll
    for (int s = 0; s < 2; s++) {
        int slot = tid + s * 256;          // 0..511
        int r = slot >> 3;                 // 0..63
        int cc = (slot & 7) << 4;          // 0,16,...,112
        cpa16(&sX[r * 128 + cc], &x[(size_t)(m0 + r) * 256 + n0 + cc]);
        cpa16(&sX[r * 128 + cc + 4], &x[(size_t)(m0 + r) * 256 + n0 + cc + 4]);
        cpa16(&sX[r * 128 + cc + 8], &x[(size_t)(m0 + r) * 256 + n0 + cc + 8]);
        cpa16(&sX[r * 128 + cc + 12], &x[(size_t)(m0 + r) * 256 + n0 + cc + 12]);
    }
    CP_COMMIT();    // group X (oldest; drains by the first CP_WAIT(1))

    auto issue = [&](int k0, int st) {
        #pragma unroll
        for (int s = 0; s < 2; s++) {          // A: 64 x 32
            int slot = tid + s * 256;
            int r = slot >> 3;
            int kk = (slot & 7) << 2;
            cpa16(&sA[st * 64 * TA_LD + r * TA_LD + kk], &An[(size_t)r * 256 + k0 + kk]);
        }
        #pragma unroll
        for (int s = 0; s < 4; s++) {          // W: 128 x 32
            int slot = tid + s * 256;
            int r = slot >> 3;
            int kk = (slot & 7) << 2;
            cpa16(&sB[st * 128 * TA_LD + r * TA_LD + kk], &Wn[(size_t)r * 256 + k0 + kk]);
        }
    };

    float acc[2][4][4] = {};
    issue(0, 0);
    CP_COMMIT();
    int p = 0;
    #pragma unroll
    for (int c = 0; c < 8; c++) {
        if (c < 7) { issue((c + 1) * 32, p ^ 1); CP_COMMIT(); CP_WAIT(1); }
        else       { CP_WAIT(0); }
        __syncthreads();
        const uint32_t* uA = (const uint32_t*)(sA + p * 64 * TA_LD);
        const uint32_t* uB = (const uint32_t*)(sB + p * 128 * TA_LD);
        #pragma unroll
        for (int ks = 0; ks < 4; ks++) {
            int kb = ks * 8;
            uint32_t a[2][4], b[4][2];
            #pragma unroll
            for (int mf = 0; mf < 2; mf++) {
                int r0 = warpM * 32 + mf * 16 + group;
                a[mf][0] = uA[r0 * TA_LD + kb + tig];
                a[mf][1] = uA[(r0 + 8) * TA_LD + kb + tig];
                a[mf][2] = uA[r0 * TA_LD + kb + tig + 4];
                a[mf][3] = uA[(r0 + 8) * TA_LD + kb + tig + 4];
            }
            #pragma unroll
            for (int nf = 0; nf < 4; nf++) {
                int nn = warpN * 32 + nf * 8 + group;
                b[nf][0] = uB[nn * TA_LD + kb + tig];
                b[nf][1] = uB[nn * TA_LD + kb + tig + 4];
            }
            #pragma unroll
            for (int mf = 0; mf < 2; mf++)
                #pragma unroll
                for (int nf = 0; nf < 4; nf++)
                    mma8(acc[mf][nf], a[mf], b[nf]);
        }
        __syncthreads();
        p ^= 1;
    }

    #pragma unroll
    for (int mf = 0; mf < 2; mf++) {
        int r0 = m0 + warpM * 32 + mf * 16 + group;
        int rl0 = warpM * 32 + mf * 16 + group;
        #pragma unroll
        for (int nf = 0; nf < 4; nf++) {
            int colL = warpN * 32 + nf * 8 + 2 * tig;
            int n = n0 + colL;
            float bv0 = Bs[n], bv1 = Bs[n + 1];
            float2 x0 = *(const float2*)&sX[rl0 * 128 + colL];
            float2 x1 = *(const float2*)&sX[(rl0 + 8) * 128 + colL];
            *(float2*)&out[(size_t)r0 * 256 + n] =
                make_float2(acc[mf][nf][0] + bv0 + x0.x, acc[mf][nf][1] + bv1 + x0.y);
            *(float2*)&out[(size_t)(r0 + 8) * 256 + n] =
                make_float2(acc[mf][nf][2] + bv0 + x1.x, acc[mf][nf][3] + bv1 + x1.y);
        }
    }
}

// ---------------------------------------------------------------------------
extern "C" void kernel_launch(void* const* d_in, const int* in_sizes, int n_in,
                              void* d_out, int out_size)
{
    (void)in_sizes; (void)n_in; (void)out_size;
    const float* x     = (const float*)d_in[0];
    const float* kp_w1 = (const float*)d_in[1];
    const float* kp_b1 = (const float*)d_in[2];
    const float* kp_w2 = (const float*)d_in[3];
    const float* kp_b2 = (const float*)d_in[4];
    const float* qp_w1 = (const float*)d_in[5];
    const float* qp_b1 = (const float*)d_in[6];
    const float* qp_w2 = (const float*)d_in[7];
    const float* qp_b2 = (const float*)d_in[8];
    const float* kh_w1 = (const float*)d_in[9];
    const float* kh_b1 = (const float*)d_in[10];
    const float* kh_w2 = (const float*)d_in[11];
    const float* kh_b2 = (const float*)d_in[12];
    const float* qh_w1 = (const float*)d_in[13];
    const float* qh_b1 = (const float*)d_in[14];
    const float* qh_w2 = (const float*)d_in[15];
    const float* qh_b2 = (const float*)d_in[16];
    const float* v_w   = (const float*)d_in[17];
    const float* v_b   = (const float*)d_in[18];
    const float* ln_g  = (const float*)d_in[19];
    const float* ln_b  = (const float*)d_in[20];
    const float* out_w = (const float*)d_in[21];
    const float* out_b = (const float*)d_in[22];
    float* out = (float*)d_out;

    float *hid, *k2, *q2, *ret, *ret2, *rln;
    cudaGetSymbolAddress((void**)&hid, g_hid);
    cudaGetSymbolAddress((void**)&k2, g_k2);
    cudaGetSymbolAddress((void**)&q2, g_q2);
    cudaGetSymbolAddress((void**)&ret, g_ret);
    cudaGetSymbolAddress((void**)&ret2, g_ret2);
    cudaGetSymbolAddress((void**)&rln, g_rln);

    static bool attr_set = false;
    if (!attr_set) {
        cudaFuncSetAttribute(gemm_fused1, cudaFuncAttributeMaxDynamicSharedMemorySize,
                             F1_SMEM_BYTES);
        cudaFuncSetAttribute(layer2_feat, cudaFuncAttributeMaxDynamicSharedMemorySize,
                             GEMM_SMEM_BYTES);
        cudaFuncSetAttribute(attn_kernel, cudaFuncAttributeMaxDynamicSharedMemorySize,
                             ATTN_SMEM_BYTES);
        cudaFuncSetAttribute(gemm_out, cudaFuncAttributeMaxDynamicSharedMemorySize,
                             OUT_SMEM_BYTES);
        attr_set = true;
    }

    dim3 blk(256);

    // 1. fused first layers + V projection (128x128 tiles, ~1 wave)
    gemm_fused1<<<dim3(32, 10), blk, F1_SMEM_BYTES>>>(
        x, kp_w1, kp_b1, qp_w1, qp_b1, kh_w1, kh_b1, qh_w1, qh_b1, v_w, v_b, hid);

    // 2. fused second layers -> phasor features
    layer2_feat<<<dim3(32, 4), blk, GEMM_SMEM_BYTES>>>(
        hid, kp_w2, kp_b2, qp_w2, qp_b2, kh_w2, kh_b2, qh_w2, qh_b2, k2, q2);

    // 3. causal linear attention — single wave, uniform 8 tiles per CTA
    attn_kernel<<<dim3(17, 2, 4), blk, ATTN_SMEM_BYTES>>>(q2, k2, hid + 1024, ret, ret2);

    // 4. fast LayerNorm (2 rows/warp)
    ln_kernel<<<256, blk>>>(ret, ret2, ln_g, ln_b, rln);

    // 5. output projection + residual (x prefetched to smem)
    gemm_out<<<dim3(64, 2), blk, OUT_SMEM_BYTES>>>(rln, out_w, out_b, x, out);
}

// round 16
// speedup vs baseline: 1.1167x; 1.0034x over previous
#include <cuda_runtime.h>
#include <math.h>
#include <stdint.h>

// B=4, L=1024, D=256, N_PER=48, N_HYP=16, K=64, features 2K=128
#define M_ROWS 4096
#define LDH 1280
#define PI_F 3.14159265358979323846f
#define TA_LD 36   // smem k-chunk stride (36 mod 32 = 4 -> conflict-free frags)

// scratch
__device__ float g_hid[M_ROWS * LDH];   // [GELU(kp|qp|kh|qh hidden) | V]
__device__ float g_k2[M_ROWS * 128];
__device__ float g_q2[M_ROWS * 128];
__device__ float g_ret[M_ROWS * 256];
__device__ float g_ret2[M_ROWS * 256];
__device__ float g_rln[M_ROWS * 256];

__device__ __forceinline__ float gelu_exact(float v) {
    return 0.5f * v * (1.0f + erff(v * 0.7071067811865475f));
}

// ---- cp.async helpers -----------------------------------------------------
__device__ __forceinline__ void cpa16(void* s, const void* g) {
    uint32_t sa = (uint32_t)__cvta_generic_to_shared(s);
    asm volatile("cp.async.cg.shared.global [%0], [%1], 16;" :: "r"(sa), "l"(g));
}
__device__ __forceinline__ void cpa16z(void* s, const void* g, int sz) {
    uint32_t sa = (uint32_t)__cvta_generic_to_shared(s);
    asm volatile("cp.async.cg.shared.global [%0], [%1], 16, %2;" :: "r"(sa), "l"(g), "r"(sz));
}
#define CP_COMMIT() asm volatile("cp.async.commit_group;" ::: "memory")
#define CP_WAIT(N)  asm volatile("cp.async.wait_group %0;" :: "n"(N) : "memory")

// raw fp32 bits fed to mma.tf32 (HW truncates to tf32)
__device__ __forceinline__ void mma8(float c[4], const uint32_t a[4], const uint32_t b[2]) {
    asm("mma.sync.aligned.m16n8k8.row.col.f32.tf32.tf32.f32 "
        "{%0,%1,%2,%3},{%4,%5,%6,%7},{%8,%9},{%0,%1,%2,%3};"
        : "+f"(c[0]), "+f"(c[1]), "+f"(c[2]), "+f"(c[3])
        : "r"(a[0]), "r"(a[1]), "r"(a[2]), "r"(a[3]), "r"(b[0]), "r"(b[1]));
}

// ===========================================================================
// Fused first layers: hid[4096,1280] = [GELU(x@W1^T+b1) x4 | x@v_w^T+v_b]
// 128x128 tiles, 2-stage pipe. grid (32, 10). warps 2(m) x 4(n).
// ===========================================================================
#define F1_SMEM_U32 (2 * 128 * TA_LD + 2 * 128 * TA_LD)   // 18432
#define F1_SMEM_BYTES (F1_SMEM_U32 * 4)                   // 73728

__global__ void __launch_bounds__(256) gemm_fused1(
    const float* __restrict__ x,
    const float* __restrict__ w0, const float* __restrict__ b0,
    const float* __restrict__ w1, const float* __restrict__ b1,
    const float* __restrict__ w2, const float* __restrict__ b2,
    const float* __restrict__ w3, const float* __restrict__ b3,
    const float* __restrict__ w4, const float* __restrict__ b4,
    float* __restrict__ hid)
{
    extern __shared__ float smf[];
    float* sA = smf;                        // 2 x 128*TA_LD
    float* sB = smf + 2 * 128 * TA_LD;      // 2 x 128*TA_LD
    const int tid = threadIdx.x, lane = tid & 31, wid = tid >> 5;
    const int group = lane >> 2, tig = lane & 3;
    const int warpM = wid & 1, warpN = wid >> 1;
    const int m0 = blockIdx.x * 128;
    const int by = blockIdx.y;
    const int seg = by >> 1;
    const int half = by & 1;

    const float* W; const float* Bs;
    if      (seg == 0) { W = w0; Bs = b0; }
    else if (seg == 1) { W = w1; Bs = b1; }
    else if (seg == 2) { W = w2; Bs = b2; }
    else if (seg == 3) { W = w3; Bs = b3; }
    else               { W = w4; Bs = b4; }
    W += (size_t)(half * 128) * 256;
    Bs += half * 128;
    const float* An = x + (size_t)m0 * 256;

    auto issue = [&](int k0, int st) {
        #pragma unroll
        for (int s = 0; s < 4; s++) {           // A: 128 x 32
            int slot = tid + s * 256;
            int r = slot >> 3;
            int kk = (slot & 7) << 2;
            cpa16(&sA[st * 128 * TA_LD + r * TA_LD + kk],
                  &An[(size_t)r * 256 + k0 + kk]);
        }
        #pragma unroll
        for (int s = 0; s < 4; s++) {           // W: 128 x 32
            int slot = tid + s * 256;
            int r = slot >> 3;
            int kk = (slot & 7) << 2;
            cpa16(&sB[st * 128 * TA_LD + r * TA_LD + kk],
                  &W[(size_t)r * 256 + k0 + kk]);
        }
    };

    float acc[4][4][4] = {};
    issue(0, 0);
    CP_COMMIT();
    int p = 0;
    #pragma unroll
    for (int c = 0; c < 8; c++) {
        if (c < 7) { issue((c + 1) * 32, p ^ 1); CP_COMMIT(); CP_WAIT(1); }
        else       { CP_WAIT(0); }
        __syncthreads();
        const uint32_t* uA = (const uint32_t*)(sA + p * 128 * TA_LD);
        const uint32_t* uB = (const uint32_t*)(sB + p * 128 * TA_LD);
        #pragma unroll
        for (int ks = 0; ks < 4; ks++) {
            int kb = ks * 8;
            uint32_t a[4][4], b[4][2];
            #pragma unroll
            for (int mf = 0; mf < 4; mf++) {
                int r0 = warpM * 64 + mf * 16 + group;
                a[mf][0] = uA[r0 * TA_LD + kb + tig];
                a[mf][1] = uA[(r0 + 8) * TA_LD + kb + tig];
                a[mf][2] = uA[r0 * TA_LD + kb + tig + 4];
                a[mf][3] = uA[(r0 + 8) * TA_LD + kb + tig + 4];
            }
            #pragma unroll
            for (int nf = 0; nf < 4; nf++) {
                int n0 = warpN * 32 + nf * 8 + group;
                b[nf][0] = uB[n0 * TA_LD + kb + tig];
                b[nf][1] = uB[n0 * TA_LD + kb + tig + 4];
            }
            #pragma unroll
            for (int mf = 0; mf < 4; mf++)
                #pragma unroll
                for (int nf = 0; nf < 4; nf++)
                    mma8(acc[mf][nf], a[mf], b[nf]);
        }
        __syncthreads();
        p ^= 1;
    }

    #pragma unroll
    for (int mf = 0; mf < 4; mf++) {
        int r0 = m0 + warpM * 64 + mf * 16 + group;
        #pragma unroll
        for (int nf = 0; nf < 4; nf++) {
            int colL = warpN * 32 + nf * 8 + 2 * tig;
            float bv0 = Bs[colL], bv1 = Bs[colL + 1];
            float v00 = acc[mf][nf][0] + bv0, v01 = acc[mf][nf][1] + bv1;
            float v10 = acc[mf][nf][2] + bv0, v11 = acc[mf][nf][3] + bv1;
            if (seg < 4) {
                v00 = gelu_exact(v00); v01 = gelu_exact(v01);
                v10 = gelu_exact(v10); v11 = gelu_exact(v11);
            }
            int gcol = by * 128 + colL;
            *(float2*)&hid[(size_t)r0 * LDH + gcol] = make_float2(v00, v01);
            *(float2*)&hid[(size_t)(r0 + 8) * LDH + gcol] = make_float2(v10, v11);
        }
    }
}

// ===========================================================================
// 128x64 tile engine (cp.async pipelined, 2-stage) — used by layer2_feat
// ===========================================================================
template <bool GUARD>
__device__ __forceinline__ void issue_chunk128(
    const float* __restrict__ A, int lda,
    const float* __restrict__ W, int nvalid, int k0,
    float* sA, float* sB)
{
    const int tid = threadIdx.x;
    #pragma unroll
    for (int s = 0; s < 4; s++) {                 // A: 128 x 32
        int slot = tid + s * 256;
        int r = slot >> 3;
        int kk = (slot & 7) << 2;
        cpa16(&sA[r * TA_LD + kk], &A[(size_t)r * lda + k0 + kk]);
    }
    #pragma unroll
    for (int s = 0; s < 2; s++) {                 // W: 64 x 32
        int slot = tid + s * 256;
        int r = slot >> 3;
        int kk = (slot & 7) << 2;
        if (GUARD) {
            int rr = (r < nvalid) ? r : 0;
            cpa16z(&sB[r * TA_LD + kk], &W[(size_t)rr * 256 + k0 + kk],
                   (r < nvalid) ? 16 : 0);
        } else {
            cpa16(&sB[r * TA_LD + kk], &W[(size_t)r * 256 + k0 + kk]);
        }
    }
}

__device__ __forceinline__ void gl_compute(
    const uint32_t* sA, const uint32_t* sB, float acc[2][4][4],
    int warpM, int warpN, int group, int tig)
{
    #pragma unroll
    for (int ks = 0; ks < 4; ks++) {
        int kb = ks * 8;
        uint32_t a[2][4], b[4][2];
        #pragma unroll
        for (int mf = 0; mf < 2; mf++) {
            int r0 = warpM * 32 + mf * 16 + group;
            a[mf][0] = sA[r0 * TA_LD + kb + tig];
            a[mf][1] = sA[(r0 + 8) * TA_LD + kb + tig];
            a[mf][2] = sA[r0 * TA_LD + kb + tig + 4];
            a[mf][3] = sA[(r0 + 8) * TA_LD + kb + tig + 4];
        }
        #pragma unroll
        for (int nf = 0; nf < 4; nf++) {
            int n0 = warpN * 32 + nf * 8 + group;
            b[nf][0] = sB[n0 * TA_LD + kb + tig];
            b[nf][1] = sB[n0 * TA_LD + kb + tig + 4];
        }
        #pragma unroll
        for (int mf = 0; mf < 2; mf++)
            #pragma unroll
            for (int nf = 0; nf < 4; nf++)
                mma8(acc[mf][nf], a[mf], b[nf]);
    }
}

#define GEMM_SMEM_U32 (2 * 128 * TA_LD + 2 * 64 * TA_LD)   // 13824
#define GEMM_SMEM_BYTES (GEMM_SMEM_U32 * 4)

template <bool GUARD>
__device__ __forceinline__ void tile_mma_pipe(
    const float* __restrict__ A, int lda,
    const float* __restrict__ W, int nvalid,
    float* smf, float acc[2][4][4],
    int warpM, int warpN, int group, int tig)
{
    float* sA = smf;                       // 2 x 128*TA_LD
    float* sB = smf + 2 * 128 * TA_LD;     // 2 x 64*TA_LD
    issue_chunk128<GUARD>(A, lda, W, nvalid, 0, sA, sB);
    CP_COMMIT();
    int p = 0;
    #pragma unroll
    for (int c = 0; c < 8; c++) {
        if (c < 7) {
            issue_chunk128<GUARD>(A, lda, W, nvalid, (c + 1) * 32,
                                  sA + (p ^ 1) * 128 * TA_LD,
                                  sB + (p ^ 1) * 64 * TA_LD);
            CP_COMMIT();
            CP_WAIT(1);
        } else {
            CP_WAIT(0);
        }
        __syncthreads();
        gl_compute((const uint32_t*)(sA + p * 128 * TA_LD),
                   (const uint32_t*)(sB + p * 64 * TA_LD), acc,
                   warpM, warpN, group, tig);
        __syncthreads();
        p ^= 1;
    }
}

// ---------------------------------------------------------------------------
// Fused second layers + phasor features -> k2/q2 [4096,128].
// grid (32, 4): seg 0=kp->k2 per, 1=qp->q2 per, 2=kh->k2 hyp, 3=qh->q2 hyp
// ---------------------------------------------------------------------------
__global__ void __launch_bounds__(256) layer2_feat(
    const float* __restrict__ hid,
    const float* __restrict__ w0, const float* __restrict__ b0,
    const float* __restrict__ w1, const float* __restrict__ b1,
    const float* __restrict__ w2, const float* __restrict__ b2,
    const float* __restrict__ w3, const float* __restrict__ b3,
    float* __restrict__ k2, float* __restrict__ q2)
{
    extern __shared__ float smf[];
    const int tid = threadIdx.x, lane = tid & 31, wid = tid >> 5;
    const int group = lane >> 2, tig = lane & 3;
    const int warpM = wid & 3, warpN = wid >> 2;
    const int m0 = blockIdx.x * 128;
    const int seg = blockIdx.y;

    const float* W; const float* Bs;
    if      (seg == 0) { W = w0; Bs = b0; }
    else if (seg == 1) { W = w1; Bs = b1; }
    else if (seg == 2) { W = w2; Bs = b2; }
    else               { W = w3; Bs = b3; }
    const int nseg = (seg < 2) ? 48 : 32;

    float acc[2][4][4] = {};
    tile_mma_pipe<true>(hid + (size_t)m0 * LDH + seg * 256, LDH, W, nseg, smf, acc,
                        warpM, warpN, group, tig);

    float* dst = (seg == 0 || seg == 2) ? k2 : q2;

    if (seg < 2) {
        #pragma unroll
        for (int mf = 0; mf < 2; mf++) {
            int r0 = m0 + warpM * 32 + mf * 16 + group;
            #pragma unroll
            for (int nf = 0; nf < 4; nf++) {
                int colL = warpN * 32 + nf * 8 + 2 * tig;
                #pragma unroll
                for (int e = 0; e < 4; e++) {
                    int n = colL + (e & 1);
                    int m = (e < 2) ? r0 : r0 + 8;
                    if (n < 48) {
                        float ang = tanhf(acc[mf][nf][e] + Bs[n]) * PI_F;
                        float s, c;
                        sincosf(ang, &s, &c);
                        dst[(size_t)m * 128 + n] = c;
                        dst[(size_t)m * 128 + 64 + n] = s;
                    }
                }
            }
        }
    } else {
        #pragma unroll
        for (int mf = 0; mf < 2; mf++) {
            int r0 = m0 + warpM * 32 + mf * 16 + group;
            #pragma unroll
            for (int nf = 0; nf < 4; nf++) {
                int colL = warpN * 32 + nf * 8 + 2 * tig;
                if (colL < 32) {
                    int jj = colL >> 1;
                    float B0 = Bs[colL], B1 = Bs[colL + 1];
                    #pragma unroll
                    for (int h = 0; h < 2; h++) {
                        int m = (h == 0) ? r0 : r0 + 8;
                        float x0 = tanhf(acc[mf][nf][2 * h + 0] + B0) * 0.9f;
                        float y0 = tanhf(acc[mf][nf][2 * h + 1] + B1) * 0.9f;
                        float r = sqrtf(x0 * x0 + y0 * y0);
                        float re, im;
                        if (r > 0.0f) {
                            float sc = (1.0f - r) / r;
                            re = x0 * sc; im = y0 * sc;
                        } else { re = 1.0f; im = 0.0f; }
                        dst[(size_t)m * 128 + 48 + jj] = re;
                        dst[(size_t)m * 128 + 112 + jj] = im;
                    }
                }
            }
        }
    }
}

// ---------------------------------------------------------------------------
// Causal linear attention, single-wave uniform schedule.
// 17 slots x (2 d-splits) x (4 batches) = 136 CTAs; every slot = exactly 8
// KV tiles, as 1 or 2 segments (qt, lo, hi). lo==0 -> ret else ret2.
// ---------------------------------------------------------------------------
__constant__ int c_seg[17][2][3] = {
    { {15, 0, 8},  {-1, 0, 0} },
    { {15, 8, 16}, {-1, 0, 0} },
    { {14, 0, 8},  {-1, 0, 0} },
    { {14, 8, 15}, {0, 0, 1} },
    { {13, 0, 8},  {-1, 0, 0} },
    { {13, 8, 14}, {1, 0, 2} },
    { {12, 0, 8},  {-1, 0, 0} },
    { {12, 8, 13}, {2, 0, 3} },
    { {11, 0, 8},  {-1, 0, 0} },
    { {11, 8, 12}, {3, 0, 4} },
    { {10, 0, 8},  {-1, 0, 0} },
    { {10, 8, 11}, {4, 0, 5} },
    { {9, 0, 8},   {-1, 0, 0} },
    { {9, 8, 10},  {5, 0, 6} },
    { {8, 0, 8},   {-1, 0, 0} },
    { {8, 8, 9},   {6, 0, 7} },
    { {7, 0, 8},   {-1, 0, 0} }
};

// floats: sQ[8448] sK0[8448] sK1[8448] sV0[8704] sV1[8704] sS[4352]
#define ATTN_SMEM_U32 (8448 * 3 + 8704 * 2 + 4352)     // 47104
#define ATTN_SMEM_BYTES (ATTN_SMEM_U32 * 4)

__global__ void __launch_bounds__(256) attn_kernel(
    const float* __restrict__ Q2, const float* __restrict__ K2,
    const float* __restrict__ Vb,   // hid + 1024, row stride LDH
    float* __restrict__ ret, float* __restrict__ ret2)
{
    extern __shared__ float smf[];
    float* sQ = smf;
    float* sK[2] = { smf + 8448, smf + 16896 };
    float* sV[2] = { smf + 25344, smf + 34048 };
    float* sS = smf + 42752;

    const int tid = threadIdx.x, lane = tid & 31, wid = tid >> 5;
    const int group = lane >> 2, tig = lane & 3;
    const int c0 = blockIdx.y * 128;
    const int b = blockIdx.z;

    const int mS = 32 * (wid >> 2), nS = 16 * (wid & 3);   // S-phase warp tile 32x16
    const int mO = 32 * (wid & 1), nO = 32 * (wid >> 1);   // O-phase warp tile 32x32

    auto issue_kv = [&](int kt, int st) {
        const int kbase = b * 1024 + kt * 64;
        #pragma unroll
        for (int s = 0; s < 8; s++) {
            int slot = tid + s * 256;
            int r = slot >> 5;
            int f = (slot & 31) << 2;
            cpa16(&sK[st][r * 132 + f], &K2[(size_t)(kbase + r) * 128 + f]);
            cpa16(&sV[st][r * 136 + f], &Vb[(size_t)(kbase + r) * LDH + c0 + f]);
        }
    };

    for (int si = 0; si < 2; si++) {
        const int qt = c_seg[blockIdx.x][si][0];
        if (qt < 0) break;
        const int lo = c_seg[blockIdx.x][si][1];
        const int hi = c_seg[blockIdx.x][si][2];
        const int qbase = b * 1024 + qt * 64;

        // load Q tile + first KV tile
        #pragma unroll
        for (int s = 0; s < 8; s++) {
            int slot = tid + s * 256;
            int r = slot >> 5;
            int f = (slot & 31) << 2;
            cpa16(&sQ[r * 132 + f], &Q2[(size_t)(qbase + r) * 128 + f]);
        }
        issue_kv(lo, 0);
        CP_COMMIT();
        CP_WAIT(0);
        __syncthreads();

        float acc[2][4][4];
        #pragma unroll
        for (int mf = 0; mf < 2; mf++)
            #pragma unroll
            for (int nf = 0; nf < 4; nf++)
                #pragma unroll
                for (int e = 0; e < 4; e++) acc[mf][nf][e] = 0.f;

        int p = 0;
        for (int kt = lo; kt < hi; kt++) {
            const bool more = (kt + 1 < hi);
            if (more) {
                issue_kv(kt + 1, p ^ 1);
                CP_COMMIT();
            }

            // S = Qtile @ Ktile^T (64x64)
            const uint32_t* sKu = (const uint32_t*)sK[p];
            const uint32_t* sQu = (const uint32_t*)sQ;
            float sacc[2][2][4];
            #pragma unroll
            for (int mf = 0; mf < 2; mf++)
                #pragma unroll
                for (int nf = 0; nf < 2; nf++)
                    #pragma unroll
                    for (int e = 0; e < 4; e++) sacc[mf][nf][e] = 0.f;

            #pragma unroll
            for (int ks = 0; ks < 16; ks++) {
                int kb = ks * 8;
                uint32_t a[2][4], bb[2][2];
                #pragma unroll
                for (int mf = 0; mf < 2; mf++) {
                    int r0 = mS + mf * 16 + group;
                    a[mf][0] = sQu[r0 * 132 + kb + tig];
                    a[mf][1] = sQu[(r0 + 8) * 132 + kb + tig];
                    a[mf][2] = sQu[r0 * 132 + kb + tig + 4];
                    a[mf][3] = sQu[(r0 + 8) * 132 + kb + tig + 4];
                }
                #pragma unroll
                for (int nf = 0; nf < 2; nf++) {
                    int n0 = nS + nf * 8 + group;
                    bb[nf][0] = sKu[n0 * 132 + kb + tig];
                    bb[nf][1] = sKu[n0 * 132 + kb + tig + 4];
                }
                #pragma unroll
                for (int mf = 0; mf < 2; mf++)
                    #pragma unroll
                    for (int nf = 0; nf < 2; nf++)
                        mma8(sacc[mf][nf], a[mf], bb[nf]);
            }

            // mask diagonal tile (inclusive causal), store S raw bits
            #pragma unroll
            for (int mf = 0; mf < 2; mf++) {
                int row = mS + mf * 16 + group;
                #pragma unroll
                for (int nf = 0; nf < 2; nf++) {
                    int col = nS + nf * 8 + 2 * tig;
                    float s0 = sacc[mf][nf][0], s1 = sacc[mf][nf][1];
                    float s2 = sacc[mf][nf][2], s3 = sacc[mf][nf][3];
                    if (kt == qt) {
                        if (col > row) s0 = 0.f;
                        if (col + 1 > row) s1 = 0.f;
                        if (col > row + 8) s2 = 0.f;
                        if (col + 1 > row + 8) s3 = 0.f;
                    }
                    *(float2*)&sS[row * 68 + col] = make_float2(s0, s1);
                    *(float2*)&sS[(row + 8) * 68 + col] = make_float2(s2, s3);
                }
            }
            __syncthreads();   // sync1: S visible; K[p] reads done

            // O += S @ Vtile (64 x 128)
            const uint32_t* sVu = (const uint32_t*)sV[p];
            const uint32_t* sSu = (const uint32_t*)sS;
            #pragma unroll
            for (int ks = 0; ks < 8; ks++) {
                int kb = ks * 8;
                uint32_t a[2][4], bb[4][2];
                #pragma unroll
                for (int mf = 0; mf < 2; mf++) {
                    int r0 = mO + mf * 16 + group;
                    a[mf][0] = sSu[r0 * 68 + kb + tig];
                    a[mf][1] = sSu[(r0 + 8) * 68 + kb + tig];
                    a[mf][2] = sSu[r0 * 68 + kb + tig + 4];
                    a[mf][3] = sSu[(r0 + 8) * 68 + kb + tig + 4];
                }
                #pragma unroll
                for (int nf = 0; nf < 4; nf++) {
                    int n0 = nO + nf * 8 + group;
                    bb[nf][0] = sVu[(kb + tig) * 136 + n0];
                    bb[nf][1] = sVu[(kb + tig + 4) * 136 + n0];
                }
                #pragma unroll
                for (int mf = 0; mf < 2; mf++)
                    #pragma unroll
                    for (int nf = 0; nf < 4; nf++)
                        mma8(acc[mf][nf], a[mf], bb[nf]);
            }

            if (more) CP_WAIT(0);
            __syncthreads();   // sync2: next stage visible; S/V[p] reads done
            p ^= 1;
        }

        // epilogue with position scale
        float* dst = (lo == 0) ? ret : ret2;
        #pragma unroll
        for (int mf = 0; mf < 2; mf++) {
            int rl = mO + mf * 16 + group;
            int row = qbase + rl;
            float sc0 = rsqrtf((float)(qt * 64 + rl + 1) * 64.0f);
            float sc1 = rsqrtf((float)(qt * 64 + rl + 9) * 64.0f);
            #pragma unroll
            for (int nf = 0; nf < 4; nf++) {
                int col = c0 + nO + nf * 8 + 2 * tig;
                *(float2*)&dst[(size_t)row * 256 + col] =
                    make_float2(acc[mf][nf][0] * sc0, acc[mf][nf][1] * sc0);
                *(float2*)&dst[(size_t)(row + 8) * 256 + col] =
                    make_float2(acc[mf][nf][2] * sc1, acc[mf][nf][3] * sc1);
            }
        }
    }
}

// ---------------------------------------------------------------------------
// Fast LayerNorm: warp handles TWO rows (doubled MLP). grid 256 x 256 thr.
// (ret already position-scaled; add ret2 for l>=512)
// ---------------------------------------------------------------------------
__global__ void __launch_bounds__(256) ln_kernel(
    const float* __restrict__ ret, const float* __restrict__ ret2,
    const float* __restrict__ g, const float* __restrict__ bta,
    float* __restrict__ rln)
{
    const int wid = threadIdx.x >> 5, lane = threadIdx.x & 31;
    const int row0 = blockIdx.x * 16 + wid * 2;   // rows row0, row0+1

    float4 v[2][2];
    #pragma unroll
    for (int rr = 0; rr < 2; rr++) {              // batch all loads first (MLP)
        int row = row0 + rr;
        const float* p0 = ret + (size_t)row * 256;
        v[rr][0] = *(const float4*)&p0[lane * 8];
        v[rr][1] = *(const float4*)&p0[lane * 8 + 4];
    }
    #pragma unroll
    for (int rr = 0; rr < 2; rr++) {
        int row = row0 + rr;
        if ((row & 1023) >= 512) {
            const float* p1 = ret2 + (size_t)row * 256;
            float4 e = *(const float4*)&p1[lane * 8];
            float4 f = *(const float4*)&p1[lane * 8 + 4];
            v[rr][0].x += e.x; v[rr][0].y += e.y; v[rr][0].z += e.z; v[rr][0].w += e.w;
            v[rr][1].x += f.x; v[rr][1].y += f.y; v[rr][1].z += f.z; v[rr][1].w += f.w;
        }
    }

    float4 g0 = *(const float4*)&g[lane * 8];
    float4 g1 = *(const float4*)&g[lane * 8 + 4];
    float4 b0 = *(const float4*)&bta[lane * 8];
    float4 b1 = *(const float4*)&bta[lane * 8 + 4];

    #pragma unroll
    for (int rr = 0; rr < 2; rr++) {
        float4 a = v[rr][0], c = v[rr][1];
        float s = a.x + a.y + a.z + a.w + c.x + c.y + c.z + c.w;
        float s2 = a.x * a.x + a.y * a.y + a.z * a.z + a.w * a.w
                 + c.x * c.x + c.y * c.y + c.z * c.z + c.w * c.w;
        #pragma unroll
        for (int o = 16; o > 0; o >>= 1) {
            s += __shfl_xor_sync(0xFFFFFFFFu, s, o);
            s2 += __shfl_xor_sync(0xFFFFFFFFu, s2, o);
        }
        float mean = s * (1.f / 256.f);
        float var = fmaxf(s2 * (1.f / 256.f) - mean * mean, 0.f);
        float rs = rsqrtf(var + 1e-5f);

        float4 o0, o1;
        o0.x = (a.x - mean) * rs * g0.x + b0.x;
        o0.y = (a.y - mean) * rs * g0.y + b0.y;
        o0.z = (a.z - mean) * rs * g0.z + b0.z;
        o0.w = (a.w - mean) * rs * g0.w + b0.w;
        o1.x = (c.x - mean) * rs * g1.x + b1.x;
        o1.y = (c.y - mean) * rs * g1.y + b1.y;
        o1.z = (c.z - mean) * rs * g1.z + b1.z;
        o1.w = (c.w - mean) * rs * g1.w + b1.w;
        float* po = rln + (size_t)(row0 + rr) * 256;
        *(float4*)&po[lane * 8] = o0;
        *(float4*)&po[lane * 8 + 4] = o1;
    }
}

// ---------------------------------------------------------------------------
// out = x + rln @ out_w^T + out_b.  64x128 tiles, grid (64, 2) = single wave.
// warps: 2(m) x 4(n), warp tile 32x32.
// ---------------------------------------------------------------------------
#define OUT_SMEM_U32 (2 * 64 * TA_LD + 2 * 128 * TA_LD)   // 13824
#define OUT_SMEM_BYTES (OUT_SMEM_U32 * 4)

__global__ void __launch_bounds__(256) gemm_out(
    const float* __restrict__ rln, const float* __restrict__ W,
    const float* __restrict__ Bs, const float* __restrict__ x,
    float* __restrict__ out)
{
    extern __shared__ float smf[];
    float* sA = smf;                      // 2 x 64*TA_LD
    float* sB = smf + 2 * 64 * TA_LD;     // 2 x 128*TA_LD
    const int tid = threadIdx.x, lane = tid & 31, wid = tid >> 5;
    const int group = lane >> 2, tig = lane & 3;
    const int warpM = wid & 1, warpN = wid >> 1;
    const int m0 = blockIdx.x * 64;
    const int n0 = blockIdx.y * 128;
    const float* An = rln + (size_t)m0 * 256;
    const float* Wn = W + (size_t)n0 * 256;

    auto issue = [&](int k0, int st) {
        #pragma unroll
        for (int s = 0; s < 2; s++) {          // A: 64 x 32
            int slot = tid + s * 256;
            int r = slot >> 3;
            int kk = (slot & 7) << 2;
            cpa16(&sA[st * 64 * TA_LD + r * TA_LD + kk], &An[(size_t)r * 256 + k0 + kk]);
        }
        #pragma unroll
        for (int s = 0; s < 4; s++) {          // W: 128 x 32
            int slot = tid + s * 256;
            int r = slot >> 3;
            int kk = (slot & 7) << 2;
            cpa16(&sB[st * 128 * TA_LD + r * TA_LD + kk], &Wn[(size_t)r * 256 + k0 + kk]);
        }
    };

    float acc[2][4][4] = {};
    issue(0, 0);
    CP_COMMIT();
    int p = 0;
    #pragma unroll
    for (int c = 0; c < 8; c++) {
        if (c < 7) { issue((c + 1) * 32, p ^ 1); CP_COMMIT(); CP_WAIT(1); }
        else       { CP_WAIT(0); }
        __syncthreads();
        const uint32_t* uA = (const uint32_t*)(sA + p * 64 * TA_LD);
        const uint32_t* uB = (const uint32_t*)(sB + p * 128 * TA_LD);
        #pragma unroll
        for (int ks = 0; ks < 4; ks++) {
            int kb = ks * 8;
            uint32_t a[2][4], b[4][2];
            #pragma unroll
            for (int mf = 0; mf < 2; mf++) {
                int r0 = warpM * 32 + mf * 16 + group;
                a[mf][0] = uA[r0 * TA_LD + kb + tig];
                a[mf][1] = uA[(r0 + 8) * TA_LD + kb + tig];
                a[mf][2] = uA[r0 * TA_LD + kb + tig + 4];
                a[mf][3] = uA[(r0 + 8) * TA_LD + kb + tig + 4];
            }
            #pragma unroll
            for (int nf = 0; nf < 4; nf++) {
                int nn = warpN * 32 + nf * 8 + group;
                b[nf][0] = uB[nn * TA_LD + kb + tig];
                b[nf][1] = uB[nn * TA_LD + kb + tig + 4];
            }
            #pragma unroll
            for (int mf = 0; mf < 2; mf++)
                #pragma unroll
                for (int nf = 0; nf < 4; nf++)
                    mma8(acc[mf][nf], a[mf], b[nf]);
        }
        __syncthreads();
        p ^= 1;
    }

    #pragma unroll
    for (int mf = 0; mf < 2; mf++) {
        int r0 = m0 + warpM * 32 + mf * 16 + group;
        #pragma unroll
        for (int nf = 0; nf < 4; nf++) {
            int n = n0 + warpN * 32 + nf * 8 + 2 * tig;
            float bv0 = Bs[n], bv1 = Bs[n + 1];
            float2 x0 = *(const float2*)&x[(size_t)r0 * 256 + n];
            float2 x1 = *(const float2*)&x[(size_t)(r0 + 8) * 256 + n];
            *(float2*)&out[(size_t)r0 * 256 + n] =
                make_float2(acc[mf][nf][0] + bv0 + x0.x, acc[mf][nf][1] + bv1 + x0.y);
            *(float2*)&out[(size_t)(r0 + 8) * 256 + n] =
                make_float2(acc[mf][nf][2] + bv0 + x1.x, acc[mf][nf][3] + bv1 + x1.y);
        }
    }
}

// ---------------------------------------------------------------------------
extern "C" void kernel_launch(void* const* d_in, const int* in_sizes, int n_in,
                              void* d_out, int out_size)
{
    (void)in_sizes; (void)n_in; (void)out_size;
    const float* x     = (const float*)d_in[0];
    const float* kp_w1 = (const float*)d_in[1];
    const float* kp_b1 = (const float*)d_in[2];
    const float* kp_w2 = (const float*)d_in[3];
    const float* kp_b2 = (const float*)d_in[4];
    const float* qp_w1 = (const float*)d_in[5];
    const float* qp_b1 = (const float*)d_in[6];
    const float* qp_w2 = (const float*)d_in[7];
    const float* qp_b2 = (const float*)d_in[8];
    const float* kh_w1 = (const float*)d_in[9];
    const float* kh_b1 = (const float*)d_in[10];
    const float* kh_w2 = (const float*)d_in[11];
    const float* kh_b2 = (const float*)d_in[12];
    const float* qh_w1 = (const float*)d_in[13];
    const float* qh_b1 = (const float*)d_in[14];
    const float* qh_w2 = (const float*)d_in[15];
    const float* qh_b2 = (const float*)d_in[16];
    const float* v_w   = (const float*)d_in[17];
    const float* v_b   = (const float*)d_in[18];
    const float* ln_g  = (const float*)d_in[19];
    const float* ln_b  = (const float*)d_in[20];
    const float* out_w = (const float*)d_in[21];
    const float* out_b = (const float*)d_in[22];
    float* out = (float*)d_out;

    float *hid, *k2, *q2, *ret, *ret2, *rln;
    cudaGetSymbolAddress((void**)&hid, g_hid);
    cudaGetSymbolAddress((void**)&k2, g_k2);
    cudaGetSymbolAddress((void**)&q2, g_q2);
    cudaGetSymbolAddress((void**)&ret, g_ret);
    cudaGetSymbolAddress((void**)&ret2, g_ret2);
    cudaGetSymbolAddress((void**)&rln, g_rln);

    static bool attr_set = false;
    if (!attr_set) {
        cudaFuncSetAttribute(gemm_fused1, cudaFuncAttributeMaxDynamicSharedMemorySize,
                             F1_SMEM_BYTES);
        cudaFuncSetAttribute(layer2_feat, cudaFuncAttributeMaxDynamicSharedMemorySize,
                             GEMM_SMEM_BYTES);
        cudaFuncSetAttribute(attn_kernel, cudaFuncAttributeMaxDynamicSharedMemorySize,
                             ATTN_SMEM_BYTES);
        cudaFuncSetAttribute(gemm_out, cudaFuncAttributeMaxDynamicSharedMemorySize,
                             OUT_SMEM_BYTES);
        attr_set = true;
    }

    dim3 blk(256);

    // 1. fused first layers + V projection (128x128 tiles, ~1 wave)
    gemm_fused1<<<dim3(32, 10), blk, F1_SMEM_BYTES>>>(
        x, kp_w1, kp_b1, qp_w1, qp_b1, kh_w1, kh_b1, qh_w1, qh_b1, v_w, v_b, hid);

    // 2. fused second layers -> phasor features
    layer2_feat<<<dim3(32, 4), blk, GEMM_SMEM_BYTES>>>(
        hid, kp_w2, kp_b2, qp_w2, qp_b2, kh_w2, kh_b2, qh_w2, qh_b2, k2, q2);

    // 3. causal linear attention — single wave, uniform 8 tiles per CTA
    attn_kernel<<<dim3(17, 2, 4), blk, ATTN_SMEM_BYTES>>>(q2, k2, hid + 1024, ret, ret2);

    // 4. fast LayerNorm (2 rows/warp)
    ln_kernel<<<256, blk>>>(ret, ret2, ln_g, ln_b, rln);

    // 5. output projection + residual (64x128 tiles, single wave)
    gemm_out<<<dim3(64, 2), blk, OUT_SMEM_BYTES>>>(rln, out_w, out_b, x, out);
}